// round 1
// baseline (speedup 1.0000x reference)
#include <cuda_runtime.h>
#include <cuda_bf16.h>

#define NV 100000
#define TT 128
#define NE 1600000
#define KK 9
#define PADW 4

// Scratch (no allocations allowed -> __device__ globals).
__device__ float g_h [(size_t)NV * TT];   // conv output (messages)
__device__ float g_sA[(size_t)NV * TT];   // aggregation ping
__device__ float g_sB[(size_t)NV * TT];   // aggregation pong
__device__ float g_cnt[NV];               // in-degree + 1 (self loop)

// ---------------------------------------------------------------------------
__global__ void init_cnt_kernel() {
    int i = blockIdx.x * blockDim.x + threadIdx.x;
    if (i < NV) g_cnt[i] = 1.0f;   // self loop contributes 1
}

__global__ void count_kernel(const int* __restrict__ ei) {
    int e = blockIdx.x * blockDim.x + threadIdx.x;
    if (e < NE) atomicAdd(&g_cnt[ei[NE + e]], 1.0f);
}

// Conv1d(K=9, same-pad) along T for one node per block (128 threads).
// If s_in != nullptr, input is relu(s_in/cnt) (fused epilogue of prev layer),
// else raw x. Writes result to BOTH h (messages) and s_out (self-loop init).
__global__ void conv_kernel(const float* __restrict__ xin,
                            const float* __restrict__ s_in,
                            const float* __restrict__ cw,
                            const float* __restrict__ cb,
                            int layer,
                            float* __restrict__ h,
                            float* __restrict__ s_out) {
    int n = blockIdx.x;
    int t = threadIdx.x;                      // 0..127
    __shared__ float row[TT + 2 * PADW];

    size_t o = (size_t)n * TT + t;
    float v;
    if (s_in) {
        float ic = 1.0f / g_cnt[n];
        v = s_in[o] * ic;
        v = v > 0.0f ? v : 0.0f;
    } else {
        v = xin[o];
    }
    row[PADW + t] = v;
    if (t < PADW) { row[t] = 0.0f; row[TT + PADW + t] = 0.0f; }
    __syncthreads();

    const float* w = cw + layer * KK;
    float acc = cb[layer];
#pragma unroll
    for (int k = 0; k < KK; k++) acc += w[k] * row[t + k];

    h[o]     = acc;
    s_out[o] = acc;
}

// One warp per edge: gather h[src] row (32 lanes x float4 = 512B) and
// vector-reduce into s[dst].
__global__ void edge_kernel(const int* __restrict__ ei,
                            const float* __restrict__ h,
                            float* __restrict__ s) {
    int gw   = (blockIdx.x * blockDim.x + threadIdx.x) >> 5;
    int lane = threadIdx.x & 31;
    if (gw >= NE) return;
    int src = __ldg(ei + gw);        // edge_index[0][e]
    int dst = __ldg(ei + NE + gw);   // edge_index[1][e]

    float4 v = *(const float4*)(h + (size_t)src * TT + lane * 4);
    float* sp = s + (size_t)dst * TT + lane * 4;
    asm volatile("red.global.add.v4.f32 [%0], {%1, %2, %3, %4};"
                 :: "l"(sp), "f"(v.x), "f"(v.y), "f"(v.z), "f"(v.w)
                 : "memory");
}

__global__ void init_out_kernel(const float* __restrict__ bout,
                                float* __restrict__ out) {
    int i = threadIdx.x;
    if (i < TT * 3) out[i] = bout[i % 3];
}

// out[i,c] += sum_j relu(s_flat[i*NV + j]/cnt) * W[c*NV + j]
// grid = (98, 128): blockIdx.y = output row i, blockIdx.x covers 1024 j each.
__global__ void reduce_kernel(const float* __restrict__ s,
                              const float* __restrict__ W,
                              float* __restrict__ out) {
    int i = blockIdx.y;
    int j = blockIdx.x * 1024 + threadIdx.x * 4;
    float c0 = 0.f, c1 = 0.f, c2 = 0.f;
    if (j < NV) {
        size_t f = (size_t)i * NV + j;
        float4 sv = *(const float4*)(s + f);
        float ic = 1.0f / g_cnt[f >> 7];               // node = flat/128
        float x0 = fmaxf(sv.x * ic, 0.f);
        float x1 = fmaxf(sv.y * ic, 0.f);
        float x2 = fmaxf(sv.z * ic, 0.f);
        float x3 = fmaxf(sv.w * ic, 0.f);
        float4 w0 = *(const float4*)(W + j);
        float4 w1 = *(const float4*)(W + NV + j);
        float4 w2 = *(const float4*)(W + 2 * NV + j);
        c0 = x0 * w0.x + x1 * w0.y + x2 * w0.z + x3 * w0.w;
        c1 = x0 * w1.x + x1 * w1.y + x2 * w1.z + x3 * w1.w;
        c2 = x0 * w2.x + x1 * w2.y + x2 * w2.z + x3 * w2.w;
    }
#pragma unroll
    for (int off = 16; off; off >>= 1) {
        c0 += __shfl_down_sync(0xFFFFFFFFu, c0, off);
        c1 += __shfl_down_sync(0xFFFFFFFFu, c1, off);
        c2 += __shfl_down_sync(0xFFFFFFFFu, c2, off);
    }
    __shared__ float sm[3][8];
    int warp = threadIdx.x >> 5, lane = threadIdx.x & 31;
    if (lane == 0) { sm[0][warp] = c0; sm[1][warp] = c1; sm[2][warp] = c2; }
    __syncthreads();
    if (threadIdx.x < 3) {
        float a = 0.f;
#pragma unroll
        for (int w = 0; w < 8; w++) a += sm[threadIdx.x][w];
        atomicAdd(&out[i * 3 + threadIdx.x], a);
    }
}

// ---------------------------------------------------------------------------
extern "C" void kernel_launch(void* const* d_in, const int* in_sizes, int n_in,
                              void* d_out, int out_size) {
    const float* x  = (const float*)d_in[0];
    const int*   ei = (const int*)  d_in[1];
    const float* cw = (const float*)d_in[2];
    const float* cb = (const float*)d_in[3];
    const float* W  = (const float*)d_in[4];
    const float* bo = (const float*)d_in[5];
    float* out = (float*)d_out;

    float *h, *sA, *sB;
    cudaGetSymbolAddress((void**)&h,  g_h);
    cudaGetSymbolAddress((void**)&sA, g_sA);
    cudaGetSymbolAddress((void**)&sB, g_sB);

    init_cnt_kernel<<<(NV + 255) / 256, 256>>>();
    count_kernel<<<(NE + 255) / 256, 256>>>(ei);

    // Layer 0: conv(x) -> h, sA(self);  scatter h -> sA
    conv_kernel<<<NV, TT>>>(x, nullptr, cw, cb, 0, h, sA);
    edge_kernel<<<NE / 8, 256>>>(ei, h, sA);

    // Layer 1: conv(relu(sA/cnt)) -> h, sB;  scatter h -> sB
    conv_kernel<<<NV, TT>>>(nullptr, sA, cw, cb, 1, h, sB);
    edge_kernel<<<NE / 8, 256>>>(ei, h, sB);

    // Layer 2: conv(relu(sB/cnt)) -> h, sA;  scatter h -> sA
    conv_kernel<<<NV, TT>>>(nullptr, sB, cw, cb, 2, h, sA);
    edge_kernel<<<NE / 8, 256>>>(ei, h, sA);

    // Final: out[i,c] = b[c] + sum_j relu(sA_flat[i*NV+j]/cnt) * W[c,j]
    init_out_kernel<<<1, TT * 3>>>(bo, out);
    reduce_kernel<<<dim3(98, TT), 256>>>(sA, W, out);
}

// round 2
// speedup vs baseline: 1.3355x; 1.3355x over previous
#include <cuda_runtime.h>
#include <cuda_bf16.h>

#define NV 100000
#define TT 128
#define NE 1600000
#define KK 9
#define PADW 4

// Scratch (no allocations allowed -> __device__ globals).
__device__ float g_hA [(size_t)NV * TT];   // ping
__device__ float g_hB [(size_t)NV * TT];   // pong
__device__ float g_xf [(size_t)NV * TT];   // final activated features
__device__ float g_inv[NV];                // 1/(deg+1)
__device__ int   g_deg[NV];
__device__ int   g_start[NV + 1];
__device__ int   g_cursor[NV];
__device__ int   g_csr[NE];                // src ids grouped by dst

// ---------------------------------------------------------------------------
__global__ void init_deg_kernel() {
    int i = blockIdx.x * blockDim.x + threadIdx.x;
    if (i < NV) g_deg[i] = 0;
}

__global__ void count_kernel(const int* __restrict__ ei) {
    int e = blockIdx.x * blockDim.x + threadIdx.x;
    if (e < NE) atomicAdd(&g_deg[ei[NE + e]], 1);
}

// Single-block exclusive scan over g_deg (98 chunks of 1024, carry in regs).
__global__ void scan_kernel() {
    __shared__ int buf[1024];
    int tid = threadIdx.x;
    int carry = 0;
    for (int base = 0; base < NV; base += 1024) {
        int i = base + tid;
        int d = (i < NV) ? g_deg[i] : 0;
        buf[tid] = d;
        __syncthreads();
#pragma unroll
        for (int off = 1; off < 1024; off <<= 1) {
            int v = (tid >= off) ? buf[tid - off] : 0;
            __syncthreads();
            buf[tid] += v;
            __syncthreads();
        }
        int incl = buf[tid];
        if (i < NV) {
            int st = carry + incl - d;
            g_start[i]  = st;
            g_cursor[i] = st;
            g_inv[i]    = 1.0f / (float)(d + 1);
        }
        int total = buf[1023];
        __syncthreads();
        carry += total;
    }
    if (tid == 0) g_start[NV] = carry;
}

__global__ void fill_kernel(const int* __restrict__ ei) {
    int e = blockIdx.x * blockDim.x + threadIdx.x;
    if (e < NE) {
        int dst = ei[NE + e];
        int pos = atomicAdd(&g_cursor[dst], 1);
        g_csr[pos] = ei[e];
    }
}

// Layer-0 conv: conv1d(x, w0) -> hA. One node per block, 128 threads.
__global__ void conv0_kernel(const float* __restrict__ xin,
                             const float* __restrict__ cw,
                             const float* __restrict__ cb,
                             float* __restrict__ h) {
    int n = blockIdx.x;
    int t = threadIdx.x;
    __shared__ float row[TT + 2 * PADW];
    size_t o = (size_t)n * TT + t;
    row[PADW + t] = xin[o];
    if (t < PADW) { row[t] = 0.0f; row[TT + PADW + t] = 0.0f; }
    __syncthreads();
    float acc = cb[0];
#pragma unroll
    for (int k = 0; k < KK; k++) acc += cw[k] * row[t + k];
    h[o] = acc;
}

// Fused: mean-aggregate (self + CSR neighbors, gather, no atomics) + relu +
// next layer's conv. 4 warps per node, float4 lanes, warp w takes every 4th edge.
__global__ void agg_conv_kernel(const float* __restrict__ hin,
                                float* __restrict__ hout,
                                const float* __restrict__ cw,
                                const float* __restrict__ cb,
                                int layer) {
    int n = blockIdx.x;
    int tid = threadIdx.x;
    int w = tid >> 5, l = tid & 31;
    int beg = g_start[n], end = g_start[n + 1];

    float4 acc;
    if (w == 0) acc = *(const float4*)(hin + (size_t)n * TT + l * 4);  // self loop
    else        acc = make_float4(0.f, 0.f, 0.f, 0.f);
    for (int k = beg + w; k < end; k += 4) {
        int s = g_csr[k];
        float4 v = *(const float4*)(hin + (size_t)s * TT + l * 4);
        acc.x += v.x; acc.y += v.y; acc.z += v.z; acc.w += v.w;
    }

    __shared__ float part[4][TT];
    *(float4*)&part[w][l * 4] = acc;
    __syncthreads();

    __shared__ float row[TT + 2 * PADW];
    float s4 = part[0][tid] + part[1][tid] + part[2][tid] + part[3][tid];
    float v = s4 * g_inv[n];
    v = v > 0.0f ? v : 0.0f;
    row[PADW + tid] = v;
    if (tid < PADW) { row[tid] = 0.0f; row[TT + PADW + tid] = 0.0f; }
    __syncthreads();

    const float* wt = cw + layer * KK;
    float r = cb[layer];
#pragma unroll
    for (int k = 0; k < KK; k++) r += wt[k] * row[tid + k];
    hout[(size_t)n * TT + tid] = r;
}

// Final aggregation (layer 2): mean + relu, no conv after; writes activated x.
__global__ void agg_final_kernel(const float* __restrict__ hin,
                                 float* __restrict__ xout) {
    int n = blockIdx.x;
    int tid = threadIdx.x;
    int w = tid >> 5, l = tid & 31;
    int beg = g_start[n], end = g_start[n + 1];

    float4 acc;
    if (w == 0) acc = *(const float4*)(hin + (size_t)n * TT + l * 4);
    else        acc = make_float4(0.f, 0.f, 0.f, 0.f);
    for (int k = beg + w; k < end; k += 4) {
        int s = g_csr[k];
        float4 v = *(const float4*)(hin + (size_t)s * TT + l * 4);
        acc.x += v.x; acc.y += v.y; acc.z += v.z; acc.w += v.w;
    }

    __shared__ float part[4][TT];
    *(float4*)&part[w][l * 4] = acc;
    __syncthreads();

    float s4 = part[0][tid] + part[1][tid] + part[2][tid] + part[3][tid];
    float v = s4 * g_inv[n];
    xout[(size_t)n * TT + tid] = v > 0.0f ? v : 0.0f;
}

__global__ void init_out_kernel(const float* __restrict__ bout,
                                float* __restrict__ out) {
    int i = threadIdx.x;
    if (i < TT * 3) out[i] = bout[i % 3];
}

// out[i,c] += sum_j xf_flat[i*NV + j] * W[c*NV + j]   (xf pre-activated)
__global__ void reduce_kernel(const float* __restrict__ xf,
                              const float* __restrict__ W,
                              float* __restrict__ out) {
    int i = blockIdx.y;
    int j = blockIdx.x * 1024 + threadIdx.x * 4;
    float c0 = 0.f, c1 = 0.f, c2 = 0.f;
    if (j < NV) {
        size_t f = (size_t)i * NV + j;
        float4 sv = *(const float4*)(xf + f);
        float4 w0 = *(const float4*)(W + j);
        float4 w1 = *(const float4*)(W + NV + j);
        float4 w2 = *(const float4*)(W + 2 * NV + j);
        c0 = sv.x * w0.x + sv.y * w0.y + sv.z * w0.z + sv.w * w0.w;
        c1 = sv.x * w1.x + sv.y * w1.y + sv.z * w1.z + sv.w * w1.w;
        c2 = sv.x * w2.x + sv.y * w2.y + sv.z * w2.z + sv.w * w2.w;
    }
#pragma unroll
    for (int off = 16; off; off >>= 1) {
        c0 += __shfl_down_sync(0xFFFFFFFFu, c0, off);
        c1 += __shfl_down_sync(0xFFFFFFFFu, c1, off);
        c2 += __shfl_down_sync(0xFFFFFFFFu, c2, off);
    }
    __shared__ float sm[3][8];
    int warp = threadIdx.x >> 5, lane = threadIdx.x & 31;
    if (lane == 0) { sm[0][warp] = c0; sm[1][warp] = c1; sm[2][warp] = c2; }
    __syncthreads();
    if (threadIdx.x < 3) {
        float a = 0.f;
#pragma unroll
        for (int w = 0; w < 8; w++) a += sm[threadIdx.x][w];
        atomicAdd(&out[i * 3 + threadIdx.x], a);
    }
}

// ---------------------------------------------------------------------------
extern "C" void kernel_launch(void* const* d_in, const int* in_sizes, int n_in,
                              void* d_out, int out_size) {
    const float* x  = (const float*)d_in[0];
    const int*   ei = (const int*)  d_in[1];
    const float* cw = (const float*)d_in[2];
    const float* cb = (const float*)d_in[3];
    const float* W  = (const float*)d_in[4];
    const float* bo = (const float*)d_in[5];
    float* out = (float*)d_out;

    float *hA, *hB, *xf;
    cudaGetSymbolAddress((void**)&hA, g_hA);
    cudaGetSymbolAddress((void**)&hB, g_hB);
    cudaGetSymbolAddress((void**)&xf, g_xf);

    // Build dst-CSR (per launch; deterministic work).
    init_deg_kernel<<<(NV + 255) / 256, 256>>>();
    count_kernel<<<(NE + 255) / 256, 256>>>(ei);
    scan_kernel<<<1, 1024>>>();
    fill_kernel<<<(NE + 255) / 256, 256>>>(ei);

    // Layer 0 conv, then fused agg+conv for layers 1, 2, then final agg.
    conv0_kernel<<<NV, TT>>>(x, cw, cb, hA);
    agg_conv_kernel<<<NV, TT>>>(hA, hB, cw, cb, 1);
    agg_conv_kernel<<<NV, TT>>>(hB, hA, cw, cb, 2);
    agg_final_kernel<<<NV, TT>>>(hA, xf);

    // Final: out[i,c] = b[c] + sum_j xf_flat[i*NV+j] * W[c,j]
    init_out_kernel<<<1, TT * 3>>>(bo, out);
    reduce_kernel<<<dim3(98, TT), 256>>>(xf, W, out);
}

// round 3
// speedup vs baseline: 3.0748x; 2.3024x over previous
#include <cuda_runtime.h>
#include <cuda_bf16.h>

#define NV 100000
#define TT 128
#define NE 1600000
#define KK 9
#define NCHUNK 98          // ceil(NV/1024)

// Scratch (no allocations allowed -> __device__ globals).
__device__ float g_hA [(size_t)NV * TT];
__device__ float g_hB [(size_t)NV * TT];
__device__ float g_xf [(size_t)NV * TT];
__device__ float g_inv[NV];
__device__ int   g_deg[NV];
__device__ int   g_start[NV + 1];
__device__ int   g_cursor[NV];
__device__ int   g_csr[NE];
__device__ int   g_csum[NCHUNK];
__device__ int   g_coff[NCHUNK];

// ---------------------------------------------------------------------------
__global__ void count_kernel(const int* __restrict__ ei) {
    int e4 = blockIdx.x * blockDim.x + threadIdx.x;
    if (e4 * 4 < NE) {
        int4 d = *(const int4*)(ei + NE + e4 * 4);
        atomicAdd(&g_deg[d.x], 1);
        atomicAdd(&g_deg[d.y], 1);
        atomicAdd(&g_deg[d.z], 1);
        atomicAdd(&g_deg[d.w], 1);
    }
}

// Phase A: per-chunk (1024 elems) degree sums.
__global__ void chunk_sum_kernel() {
    int i = blockIdx.x * 1024 + threadIdx.x;
    int d = (i < NV) ? g_deg[i] : 0;
#pragma unroll
    for (int off = 16; off; off >>= 1) d += __shfl_down_sync(~0u, d, off);
    __shared__ int ws[32];
    int w = threadIdx.x >> 5, l = threadIdx.x & 31;
    if (l == 0) ws[w] = d;
    __syncthreads();
    if (threadIdx.x < 32) {
        int v = ws[threadIdx.x];
#pragma unroll
        for (int off = 16; off; off >>= 1) v += __shfl_down_sync(~0u, v, off);
        if (threadIdx.x == 0) g_csum[blockIdx.x] = v;
    }
}

// Phase B: scan 98 chunk sums (one block, 128 threads).
__global__ void chunk_scan_kernel() {
    __shared__ int buf[128];
    int t = threadIdx.x;
    int v = (t < NCHUNK) ? g_csum[t] : 0;
    buf[t] = v;
    __syncthreads();
#pragma unroll
    for (int off = 1; off < 128; off <<= 1) {
        int u = (t >= off) ? buf[t - off] : 0;
        __syncthreads();
        buf[t] += u;
        __syncthreads();
    }
    if (t < NCHUNK) g_coff[t] = buf[t] - v;   // exclusive
    if (t == 0) g_start[NV] = NE;
}

// Phase C: per-chunk inclusive scan -> global start/cursor/inv.
__global__ void chunk_fill_kernel() {
    int i = blockIdx.x * 1024 + threadIdx.x;
    int d = (i < NV) ? g_deg[i] : 0;
    int l = threadIdx.x & 31, w = threadIdx.x >> 5;
    int s = d;
#pragma unroll
    for (int off = 1; off < 32; off <<= 1) {
        int u = __shfl_up_sync(~0u, s, off);
        if (l >= off) s += u;
    }
    __shared__ int ws[32];
    if (l == 31) ws[w] = s;
    __syncthreads();
    if (threadIdx.x < 32) {
        int v = ws[threadIdx.x];
#pragma unroll
        for (int off = 1; off < 32; off <<= 1) {
            int u = __shfl_up_sync(~0u, v, off);
            if (threadIdx.x >= off) v += u;
        }
        ws[threadIdx.x] = v;
    }
    __syncthreads();
    int incl = s + (w ? ws[w - 1] : 0) + g_coff[blockIdx.x];
    if (i < NV) {
        int st = incl - d;
        g_start[i]  = st;
        g_cursor[i] = st;
        g_inv[i]    = 1.0f / (float)(d + 1);
    }
}

__global__ void fill_kernel(const int* __restrict__ ei) {
    int e4 = blockIdx.x * blockDim.x + threadIdx.x;
    if (e4 * 4 < NE) {
        int4 s = *(const int4*)(ei + e4 * 4);
        int4 d = *(const int4*)(ei + NE + e4 * 4);
        g_csr[atomicAdd(&g_cursor[d.x], 1)] = s.x;
        g_csr[atomicAdd(&g_cursor[d.y], 1)] = s.y;
        g_csr[atomicAdd(&g_cursor[d.z], 1)] = s.z;
        g_csr[atomicAdd(&g_cursor[d.w], 1)] = s.w;
    }
}

// Register conv1d (K=9) across a warp-held row: lane l holds t=4l..4l+3.
__device__ __forceinline__ float4 conv_shfl(float4 v, const float* __restrict__ wt,
                                            float bias, int lane) {
    float c[12];
    c[4] = v.x; c[5] = v.y; c[6] = v.z; c[7] = v.w;
    c[0] = __shfl_up_sync(~0u, v.x, 1);
    c[1] = __shfl_up_sync(~0u, v.y, 1);
    c[2] = __shfl_up_sync(~0u, v.z, 1);
    c[3] = __shfl_up_sync(~0u, v.w, 1);
    c[8]  = __shfl_down_sync(~0u, v.x, 1);
    c[9]  = __shfl_down_sync(~0u, v.y, 1);
    c[10] = __shfl_down_sync(~0u, v.z, 1);
    c[11] = __shfl_down_sync(~0u, v.w, 1);
    if (lane == 0)  { c[0] = c[1] = c[2] = c[3] = 0.f; }
    if (lane == 31) { c[8] = c[9] = c[10] = c[11] = 0.f; }
    float4 r;
    r.x = bias; r.y = bias; r.z = bias; r.w = bias;
#pragma unroll
    for (int k = 0; k < KK; k++) {
        r.x += wt[k] * c[k];
        r.y += wt[k] * c[k + 1];
        r.z += wt[k] * c[k + 2];
        r.w += wt[k] * c[k + 3];
    }
    return r;
}

// Layer-0 conv: warp per node.
__global__ void conv0_kernel(const float* __restrict__ xin,
                             const float* __restrict__ cw,
                             const float* __restrict__ cb,
                             float* __restrict__ h) {
    int n = blockIdx.x * 8 + (threadIdx.x >> 5);
    int lane = threadIdx.x & 31;
    if (n >= NV) return;
    float wt[KK];
#pragma unroll
    for (int k = 0; k < KK; k++) wt[k] = cw[k];
    float4 v = *(const float4*)(xin + (size_t)n * TT + lane * 4);
    float4 r = conv_shfl(v, wt, cb[0], lane);
    *(float4*)(h + (size_t)n * TT + lane * 4) = r;
}

// Fused agg (gather CSR, warp per node, no barriers) + mean + relu [+ conv].
template <bool DO_CONV>
__global__ void agg_kernel(const float* __restrict__ hin,
                           float* __restrict__ hout,
                           const float* __restrict__ cw,
                           const float* __restrict__ cb,
                           int layer) {
    int n = blockIdx.x * 8 + (threadIdx.x >> 5);
    int lane = threadIdx.x & 31;
    if (n >= NV) return;
    int beg = g_start[n], end = g_start[n + 1];
    size_t lo = (size_t)lane * 4;

    float4 acc = *(const float4*)(hin + (size_t)n * TT + lo);   // self loop
    int k = beg;
    for (; k + 4 <= end; k += 4) {
        int s0 = g_csr[k], s1 = g_csr[k + 1], s2 = g_csr[k + 2], s3 = g_csr[k + 3];
        float4 a = *(const float4*)(hin + (size_t)s0 * TT + lo);
        float4 b = *(const float4*)(hin + (size_t)s1 * TT + lo);
        float4 c = *(const float4*)(hin + (size_t)s2 * TT + lo);
        float4 d = *(const float4*)(hin + (size_t)s3 * TT + lo);
        acc.x += a.x + b.x + c.x + d.x;
        acc.y += a.y + b.y + c.y + d.y;
        acc.z += a.z + b.z + c.z + d.z;
        acc.w += a.w + b.w + c.w + d.w;
    }
    for (; k < end; k++) {
        int s = g_csr[k];
        float4 a = *(const float4*)(hin + (size_t)s * TT + lo);
        acc.x += a.x; acc.y += a.y; acc.z += a.z; acc.w += a.w;
    }

    float inv = g_inv[n];
    float4 v;
    v.x = fmaxf(acc.x * inv, 0.f);
    v.y = fmaxf(acc.y * inv, 0.f);
    v.z = fmaxf(acc.z * inv, 0.f);
    v.w = fmaxf(acc.w * inv, 0.f);

    if (DO_CONV) {
        float wt[KK];
#pragma unroll
        for (int q = 0; q < KK; q++) wt[q] = cw[layer * KK + q];
        v = conv_shfl(v, wt, cb[layer], lane);
    }
    *(float4*)(hout + (size_t)n * TT + lo) = v;
}

__global__ void init_out_kernel(const float* __restrict__ bout,
                                float* __restrict__ out) {
    int i = threadIdx.x;
    if (i < TT * 3) out[i] = bout[i % 3];
}

// out[i,c] += sum_j xf_flat[i*NV + j] * W[c*NV + j]
__global__ void reduce_kernel(const float* __restrict__ xf,
                              const float* __restrict__ W,
                              float* __restrict__ out) {
    int i = blockIdx.y;
    int j = blockIdx.x * 1024 + threadIdx.x * 4;
    float c0 = 0.f, c1 = 0.f, c2 = 0.f;
    if (j < NV) {
        size_t f = (size_t)i * NV + j;
        float4 sv = *(const float4*)(xf + f);
        float4 w0 = *(const float4*)(W + j);
        float4 w1 = *(const float4*)(W + NV + j);
        float4 w2 = *(const float4*)(W + 2 * NV + j);
        c0 = sv.x * w0.x + sv.y * w0.y + sv.z * w0.z + sv.w * w0.w;
        c1 = sv.x * w1.x + sv.y * w1.y + sv.z * w1.z + sv.w * w1.w;
        c2 = sv.x * w2.x + sv.y * w2.y + sv.z * w2.z + sv.w * w2.w;
    }
#pragma unroll
    for (int off = 16; off; off >>= 1) {
        c0 += __shfl_down_sync(~0u, c0, off);
        c1 += __shfl_down_sync(~0u, c1, off);
        c2 += __shfl_down_sync(~0u, c2, off);
    }
    __shared__ float sm[3][8];
    int warp = threadIdx.x >> 5, lane = threadIdx.x & 31;
    if (lane == 0) { sm[0][warp] = c0; sm[1][warp] = c1; sm[2][warp] = c2; }
    __syncthreads();
    if (threadIdx.x < 3) {
        float a = 0.f;
#pragma unroll
        for (int w = 0; w < 8; w++) a += sm[threadIdx.x][w];
        atomicAdd(&out[i * 3 + threadIdx.x], a);
    }
}

// ---------------------------------------------------------------------------
extern "C" void kernel_launch(void* const* d_in, const int* in_sizes, int n_in,
                              void* d_out, int out_size) {
    const float* x  = (const float*)d_in[0];
    const int*   ei = (const int*)  d_in[1];
    const float* cw = (const float*)d_in[2];
    const float* cb = (const float*)d_in[3];
    const float* W  = (const float*)d_in[4];
    const float* bo = (const float*)d_in[5];
    float* out = (float*)d_out;

    float *hA, *hB, *xf;
    void* degp;
    cudaGetSymbolAddress((void**)&hA, g_hA);
    cudaGetSymbolAddress((void**)&hB, g_hB);
    cudaGetSymbolAddress((void**)&xf, g_xf);
    cudaGetSymbolAddress(&degp, g_deg);

    // Build dst-CSR.
    cudaMemsetAsync(degp, 0, NV * sizeof(int));
    count_kernel<<<(NE / 4 + 255) / 256, 256>>>(ei);
    chunk_sum_kernel<<<NCHUNK, 1024>>>();
    chunk_scan_kernel<<<1, 128>>>();
    chunk_fill_kernel<<<NCHUNK, 1024>>>();
    fill_kernel<<<(NE / 4 + 255) / 256, 256>>>(ei);

    int gagg = (NV + 7) / 8;
    conv0_kernel<<<gagg, 256>>>(x, cw, cb, hA);
    agg_kernel<true ><<<gagg, 256>>>(hA, hB, cw, cb, 1);
    agg_kernel<true ><<<gagg, 256>>>(hB, hA, cw, cb, 2);
    agg_kernel<false><<<gagg, 256>>>(hA, xf, cw, cb, 0);

    init_out_kernel<<<1, TT * 3>>>(bo, out);
    reduce_kernel<<<dim3(98, TT), 256>>>(xf, W, out);
}

// round 7
// speedup vs baseline: 3.1473x; 1.0236x over previous
#include <cuda_runtime.h>
#include <cuda_bf16.h>

#define NV 100000
#define TT 128
#define NE 1600000
#define KK 9
#define NCHUNK 98          // ceil(NV/1024)

// Scratch (no allocations allowed -> __device__ globals).
__device__ float g_hA [(size_t)NV * TT];
__device__ float g_hB [(size_t)NV * TT];
__device__ float g_inv[NV];
__device__ int   g_deg[NV];
__device__ int   g_start[NV + 1];
__device__ int   g_cursor[NV];
__device__ int   g_csr[NE];
__device__ int   g_csum[NCHUNK];
__device__ int   g_coff[NCHUNK];

// ---------------------------------------------------------------------------
__global__ void count_kernel(const int* __restrict__ ei) {
    int e4 = blockIdx.x * blockDim.x + threadIdx.x;
    if (e4 * 4 < NE) {
        int4 d = *(const int4*)(ei + NE + e4 * 4);
        atomicAdd(&g_deg[d.x], 1);
        atomicAdd(&g_deg[d.y], 1);
        atomicAdd(&g_deg[d.z], 1);
        atomicAdd(&g_deg[d.w], 1);
    }
}

__global__ void chunk_sum_kernel() {
    int i = blockIdx.x * 1024 + threadIdx.x;
    int d = (i < NV) ? g_deg[i] : 0;
#pragma unroll
    for (int off = 16; off; off >>= 1) d += __shfl_down_sync(~0u, d, off);
    __shared__ int ws[32];
    int w = threadIdx.x >> 5, l = threadIdx.x & 31;
    if (l == 0) ws[w] = d;
    __syncthreads();
    if (threadIdx.x < 32) {
        int v = ws[threadIdx.x];
#pragma unroll
        for (int off = 16; off; off >>= 1) v += __shfl_down_sync(~0u, v, off);
        if (threadIdx.x == 0) g_csum[blockIdx.x] = v;
    }
}

__global__ void chunk_scan_kernel() {
    __shared__ int buf[128];
    int t = threadIdx.x;
    int v = (t < NCHUNK) ? g_csum[t] : 0;
    buf[t] = v;
    __syncthreads();
#pragma unroll
    for (int off = 1; off < 128; off <<= 1) {
        int u = (t >= off) ? buf[t - off] : 0;
        __syncthreads();
        buf[t] += u;
        __syncthreads();
    }
    if (t < NCHUNK) g_coff[t] = buf[t] - v;   // exclusive
    if (t == 0) g_start[NV] = NE;
}

__global__ void chunk_fill_kernel() {
    int i = blockIdx.x * 1024 + threadIdx.x;
    int d = (i < NV) ? g_deg[i] : 0;
    int l = threadIdx.x & 31, w = threadIdx.x >> 5;
    int s = d;
#pragma unroll
    for (int off = 1; off < 32; off <<= 1) {
        int u = __shfl_up_sync(~0u, s, off);
        if (l >= off) s += u;
    }
    __shared__ int ws[32];
    if (l == 31) ws[w] = s;
    __syncthreads();
    if (threadIdx.x < 32) {
        int v = ws[threadIdx.x];
#pragma unroll
        for (int off = 1; off < 32; off <<= 1) {
            int u = __shfl_up_sync(~0u, v, off);
            if (threadIdx.x >= off) v += u;
        }
        ws[threadIdx.x] = v;
    }
    __syncthreads();
    int incl = s + (w ? ws[w - 1] : 0) + g_coff[blockIdx.x];
    if (i < NV) {
        int st = incl - d;
        g_start[i]  = st;
        g_cursor[i] = st;
        g_inv[i]    = 1.0f / (float)(d + 1);
    }
}

__global__ void fill_kernel(const int* __restrict__ ei) {
    int e4 = blockIdx.x * blockDim.x + threadIdx.x;
    if (e4 * 4 < NE) {
        int4 s = *(const int4*)(ei + e4 * 4);
        int4 d = *(const int4*)(ei + NE + e4 * 4);
        g_csr[atomicAdd(&g_cursor[d.x], 1)] = s.x;
        g_csr[atomicAdd(&g_cursor[d.y], 1)] = s.y;
        g_csr[atomicAdd(&g_cursor[d.z], 1)] = s.z;
        g_csr[atomicAdd(&g_cursor[d.w], 1)] = s.w;
    }
}

// ---------------------------------------------------------------------------
// Register conv1d (K=9) across a warp-held row: lane l holds t=4l..4l+3.
__device__ __forceinline__ float4 conv_shfl(float4 v, const float* __restrict__ wt,
                                            float bias, int lane) {
    float c[12];
    c[4] = v.x; c[5] = v.y; c[6] = v.z; c[7] = v.w;
    c[0] = __shfl_up_sync(~0u, v.x, 1);
    c[1] = __shfl_up_sync(~0u, v.y, 1);
    c[2] = __shfl_up_sync(~0u, v.z, 1);
    c[3] = __shfl_up_sync(~0u, v.w, 1);
    c[8]  = __shfl_down_sync(~0u, v.x, 1);
    c[9]  = __shfl_down_sync(~0u, v.y, 1);
    c[10] = __shfl_down_sync(~0u, v.z, 1);
    c[11] = __shfl_down_sync(~0u, v.w, 1);
    if (lane == 0)  { c[0] = c[1] = c[2] = c[3] = 0.f; }
    if (lane == 31) { c[8] = c[9] = c[10] = c[11] = 0.f; }
    float4 r;
    r.x = bias; r.y = bias; r.z = bias; r.w = bias;
#pragma unroll
    for (int k = 0; k < KK; k++) {
        r.x += wt[k] * c[k];
        r.y += wt[k] * c[k + 1];
        r.z += wt[k] * c[k + 2];
        r.w += wt[k] * c[k + 3];
    }
    return r;
}

// Gather-aggregate one node's neighborhood (self + CSR), fp32.
__device__ __forceinline__ float4 aggregate(const float* __restrict__ hin,
                                            int n, int lane) {
    int beg = g_start[n], end = g_start[n + 1];
    size_t lo = (size_t)lane * 4;
    float4 acc = *(const float4*)(hin + (size_t)n * TT + lo);   // self loop
    int k = beg;
    for (; k + 4 <= end; k += 4) {
        int s0 = g_csr[k], s1 = g_csr[k + 1], s2 = g_csr[k + 2], s3 = g_csr[k + 3];
        float4 a = *(const float4*)(hin + (size_t)s0 * TT + lo);
        float4 b = *(const float4*)(hin + (size_t)s1 * TT + lo);
        float4 c = *(const float4*)(hin + (size_t)s2 * TT + lo);
        float4 d = *(const float4*)(hin + (size_t)s3 * TT + lo);
        acc.x += a.x + b.x + c.x + d.x;
        acc.y += a.y + b.y + c.y + d.y;
        acc.z += a.z + b.z + c.z + d.z;
        acc.w += a.w + b.w + c.w + d.w;
    }
    for (; k < end; k++) {
        int s = g_csr[k];
        float4 a = *(const float4*)(hin + (size_t)s * TT + lo);
        acc.x += a.x; acc.y += a.y; acc.z += a.z; acc.w += a.w;
    }
    return acc;
}

// Layer-0 conv: warp per node.
__global__ void conv0_kernel(const float* __restrict__ xin,
                             const float* __restrict__ cw,
                             const float* __restrict__ cb,
                             float* __restrict__ h) {
    int n = blockIdx.x * 8 + (threadIdx.x >> 5);
    int lane = threadIdx.x & 31;
    if (n >= NV) return;
    float wt[KK];
#pragma unroll
    for (int k = 0; k < KK; k++) wt[k] = cw[k];
    float4 v = *(const float4*)(xin + (size_t)n * TT + lane * 4);
    float4 r = conv_shfl(v, wt, cb[0], lane);
    *(float4*)(h + (size_t)n * TT + lane * 4) = r;
}

// Fused agg + mean + relu + next conv (layers 1, 2).
__global__ void agg_conv_kernel(const float* __restrict__ hin,
                                float* __restrict__ hout,
                                const float* __restrict__ cw,
                                const float* __restrict__ cb,
                                int layer) {
    int n = blockIdx.x * 8 + (threadIdx.x >> 5);
    int lane = threadIdx.x & 31;
    if (n >= NV) return;
    float4 acc = aggregate(hin, n, lane);
    float inv = g_inv[n];
    float4 v;
    v.x = fmaxf(acc.x * inv, 0.f);
    v.y = fmaxf(acc.y * inv, 0.f);
    v.z = fmaxf(acc.z * inv, 0.f);
    v.w = fmaxf(acc.w * inv, 0.f);
    float wt[KK];
#pragma unroll
    for (int q = 0; q < KK; q++) wt[q] = cw[layer * KK + q];
    v = conv_shfl(v, wt, cb[layer], lane);
    *(float4*)(hout + (size_t)n * TT + lane * 4) = v;
}

__global__ void init_out_kernel(const float* __restrict__ bout,
                                float* __restrict__ out) {
    int i = threadIdx.x;
    if (i < TT * 3) out[i] = bout[i % 3];
}

// Fused final agg + mean + relu + output matvec with CORRECT reshape
// semantics: value of node n at time t sits at flat position f = n*128+t
// of x.reshape(T_out=128, NV); it contributes to out[i = f/NV, c] with
// weight W[c*NV + (f%NV)]. Within one node-row, i takes at most 2 values.
__global__ void agg_out_kernel(const float* __restrict__ hin,
                               const float* __restrict__ W,
                               float* __restrict__ out) {
    __shared__ float sm[8][TT * 3];   // per-warp accumulator banks
    int w = threadIdx.x >> 5, lane = threadIdx.x & 31;
    for (int i = threadIdx.x; i < 8 * TT * 3; i += 256)
        ((float*)sm)[i] = 0.f;
    __syncthreads();

    int stride = gridDim.x * 8;
    for (int n = blockIdx.x * 8 + w; n < NV; n += stride) {
        float4 acc = aggregate(hin, n, lane);
        float inv = g_inv[n];
        float v[4];
        v[0] = fmaxf(acc.x * inv, 0.f);
        v[1] = fmaxf(acc.y * inv, 0.f);
        v[2] = fmaxf(acc.z * inv, 0.f);
        v[3] = fmaxf(acc.w * inv, 0.f);

        int fbase = n * TT;              // flat index of t=0 (max 12.8M, fits int)
        int i0 = fbase / NV;             // output row for row start
        int B  = (i0 + 1) * NV;          // flat boundary to row i0+1
        int f  = fbase + lane * 4;
        float s0[3] = {0.f, 0.f, 0.f}, s1[3] = {0.f, 0.f, 0.f};
#pragma unroll
        for (int q = 0; q < 4; q++) {
            int fq = f + q;
            bool hi = fq >= B;
            int j = fq - (hi ? B : i0 * NV);
            float w0 = __ldg(W + j);
            float w1 = __ldg(W + NV + j);
            float w2 = __ldg(W + 2 * NV + j);
            if (hi) { s1[0] += v[q] * w0; s1[1] += v[q] * w1; s1[2] += v[q] * w2; }
            else    { s0[0] += v[q] * w0; s0[1] += v[q] * w1; s0[2] += v[q] * w2; }
        }
#pragma unroll
        for (int off = 16; off; off >>= 1) {
            s0[0] += __shfl_down_sync(~0u, s0[0], off);
            s0[1] += __shfl_down_sync(~0u, s0[1], off);
            s0[2] += __shfl_down_sync(~0u, s0[2], off);
            s1[0] += __shfl_down_sync(~0u, s1[0], off);
            s1[1] += __shfl_down_sync(~0u, s1[1], off);
            s1[2] += __shfl_down_sync(~0u, s1[2], off);
        }
        if (lane == 0) {
            sm[w][i0 * 3 + 0] += s0[0];
            sm[w][i0 * 3 + 1] += s0[1];
            sm[w][i0 * 3 + 2] += s0[2];
            if (B < fbase + TT) {        // row split inside this node (i0+1 <= 127)
                sm[w][(i0 + 1) * 3 + 0] += s1[0];
                sm[w][(i0 + 1) * 3 + 1] += s1[1];
                sm[w][(i0 + 1) * 3 + 2] += s1[2];
            }
        }
    }
    __syncthreads();
    for (int i = threadIdx.x; i < TT * 3; i += 256) {
        float s = 0.f;
#pragma unroll
        for (int ww = 0; ww < 8; ww++) s += sm[ww][i];
        atomicAdd(&out[i], s);
    }
}

// ---------------------------------------------------------------------------
extern "C" void kernel_launch(void* const* d_in, const int* in_sizes, int n_in,
                              void* d_out, int out_size) {
    const float* x  = (const float*)d_in[0];
    const int*   ei = (const int*)  d_in[1];
    const float* cw = (const float*)d_in[2];
    const float* cb = (const float*)d_in[3];
    const float* W  = (const float*)d_in[4];
    const float* bo = (const float*)d_in[5];
    float* out = (float*)d_out;

    float *hA, *hB;
    void* degp;
    cudaGetSymbolAddress((void**)&hA, g_hA);
    cudaGetSymbolAddress((void**)&hB, g_hB);
    cudaGetSymbolAddress(&degp, g_deg);

    // Build dst-CSR.
    cudaMemsetAsync(degp, 0, NV * sizeof(int));
    count_kernel<<<(NE / 4 + 255) / 256, 256>>>(ei);
    chunk_sum_kernel<<<NCHUNK, 1024>>>();
    chunk_scan_kernel<<<1, 128>>>();
    chunk_fill_kernel<<<NCHUNK, 1024>>>();
    fill_kernel<<<(NE / 4 + 255) / 256, 256>>>(ei);

    int gagg = (NV + 7) / 8;
    conv0_kernel<<<gagg, 256>>>(x, cw, cb, hA);
    agg_conv_kernel<<<gagg, 256>>>(hA, hB, cw, cb, 1);
    agg_conv_kernel<<<gagg, 256>>>(hB, hA, cw, cb, 2);

    init_out_kernel<<<1, TT * 3>>>(bo, out);
    agg_out_kernel<<<592, 256>>>(hA, W, out);
}

// round 8
// speedup vs baseline: 3.8051x; 1.2090x over previous
#include <cuda_runtime.h>
#include <cuda_fp16.h>
#include <cuda_bf16.h>

#define NV 100000
#define TT 128
#define NE 1600000
#define KK 9
#define NCHUNK 98          // ceil(NV/1024)

// Scratch (no allocations allowed -> __device__ globals).
__device__ __half g_hA [(size_t)NV * TT];   // fp16 ping (25.6MB)
__device__ __half g_hB [(size_t)NV * TT];   // fp16 pong (25.6MB)
__device__ float  g_inv[NV];
__device__ int    g_deg[NV];
__device__ int    g_start[NV + 1];
__device__ int    g_cursor[NV];
__device__ int    g_csr[NE];
__device__ int    g_csum[NCHUNK];
__device__ int    g_coff[NCHUNK];

// ---------------------------------------------------------------------------
__global__ void count_kernel(const int* __restrict__ ei) {
    int e4 = blockIdx.x * blockDim.x + threadIdx.x;
    if (e4 * 4 < NE) {
        int4 d = *(const int4*)(ei + NE + e4 * 4);
        atomicAdd(&g_deg[d.x], 1);
        atomicAdd(&g_deg[d.y], 1);
        atomicAdd(&g_deg[d.z], 1);
        atomicAdd(&g_deg[d.w], 1);
    }
}

__global__ void chunk_sum_kernel() {
    int i = blockIdx.x * 1024 + threadIdx.x;
    int d = (i < NV) ? g_deg[i] : 0;
#pragma unroll
    for (int off = 16; off; off >>= 1) d += __shfl_down_sync(~0u, d, off);
    __shared__ int ws[32];
    int w = threadIdx.x >> 5, l = threadIdx.x & 31;
    if (l == 0) ws[w] = d;
    __syncthreads();
    if (threadIdx.x < 32) {
        int v = ws[threadIdx.x];
#pragma unroll
        for (int off = 16; off; off >>= 1) v += __shfl_down_sync(~0u, v, off);
        if (threadIdx.x == 0) g_csum[blockIdx.x] = v;
    }
}

__global__ void chunk_scan_kernel() {
    __shared__ int buf[128];
    int t = threadIdx.x;
    int v = (t < NCHUNK) ? g_csum[t] : 0;
    buf[t] = v;
    __syncthreads();
#pragma unroll
    for (int off = 1; off < 128; off <<= 1) {
        int u = (t >= off) ? buf[t - off] : 0;
        __syncthreads();
        buf[t] += u;
        __syncthreads();
    }
    if (t < NCHUNK) g_coff[t] = buf[t] - v;   // exclusive
    if (t == 0) g_start[NV] = NE;
}

__global__ void chunk_fill_kernel() {
    int i = blockIdx.x * 1024 + threadIdx.x;
    int d = (i < NV) ? g_deg[i] : 0;
    int l = threadIdx.x & 31, w = threadIdx.x >> 5;
    int s = d;
#pragma unroll
    for (int off = 1; off < 32; off <<= 1) {
        int u = __shfl_up_sync(~0u, s, off);
        if (l >= off) s += u;
    }
    __shared__ int ws[32];
    if (l == 31) ws[w] = s;
    __syncthreads();
    if (threadIdx.x < 32) {
        int v = ws[threadIdx.x];
#pragma unroll
        for (int off = 1; off < 32; off <<= 1) {
            int u = __shfl_up_sync(~0u, v, off);
            if (threadIdx.x >= off) v += u;
        }
        ws[threadIdx.x] = v;
    }
    __syncthreads();
    int incl = s + (w ? ws[w - 1] : 0) + g_coff[blockIdx.x];
    if (i < NV) {
        int st = incl - d;
        g_start[i]  = st;
        g_cursor[i] = st;
        g_inv[i]    = 1.0f / (float)(d + 1);
    }
}

__global__ void fill_kernel(const int* __restrict__ ei) {
    int e4 = blockIdx.x * blockDim.x + threadIdx.x;
    if (e4 * 4 < NE) {
        int4 s = *(const int4*)(ei + e4 * 4);
        int4 d = *(const int4*)(ei + NE + e4 * 4);
        g_csr[atomicAdd(&g_cursor[d.x], 1)] = s.x;
        g_csr[atomicAdd(&g_cursor[d.y], 1)] = s.y;
        g_csr[atomicAdd(&g_cursor[d.z], 1)] = s.z;
        g_csr[atomicAdd(&g_cursor[d.w], 1)] = s.w;
    }
}

// ---------------------------------------------------------------------------
// fp16 row helpers: lane l holds t = 4l..4l+3 (8 bytes per lane).
__device__ __forceinline__ void acc_u2(float4& acc, uint2 u) {
    float2 a = __half22float2(*reinterpret_cast<__half2*>(&u.x));
    float2 b = __half22float2(*reinterpret_cast<__half2*>(&u.y));
    acc.x += a.x; acc.y += a.y; acc.z += b.x; acc.w += b.y;
}

__device__ __forceinline__ void store_row(__half* __restrict__ h, int n, int lane,
                                          float4 v) {
    uint2 u;
    *reinterpret_cast<__half2*>(&u.x) = __floats2half2_rn(v.x, v.y);
    *reinterpret_cast<__half2*>(&u.y) = __floats2half2_rn(v.z, v.w);
    *(uint2*)(h + (size_t)n * TT + lane * 4) = u;
}

// Register conv1d (K=9) across a warp-held row (fp32).
__device__ __forceinline__ float4 conv_shfl(float4 v, const float* __restrict__ wt,
                                            float bias, int lane) {
    float c[12];
    c[4] = v.x; c[5] = v.y; c[6] = v.z; c[7] = v.w;
    c[0] = __shfl_up_sync(~0u, v.x, 1);
    c[1] = __shfl_up_sync(~0u, v.y, 1);
    c[2] = __shfl_up_sync(~0u, v.z, 1);
    c[3] = __shfl_up_sync(~0u, v.w, 1);
    c[8]  = __shfl_down_sync(~0u, v.x, 1);
    c[9]  = __shfl_down_sync(~0u, v.y, 1);
    c[10] = __shfl_down_sync(~0u, v.z, 1);
    c[11] = __shfl_down_sync(~0u, v.w, 1);
    if (lane == 0)  { c[0] = c[1] = c[2] = c[3] = 0.f; }
    if (lane == 31) { c[8] = c[9] = c[10] = c[11] = 0.f; }
    float4 r;
    r.x = bias; r.y = bias; r.z = bias; r.w = bias;
#pragma unroll
    for (int k = 0; k < KK; k++) {
        r.x += wt[k] * c[k];
        r.y += wt[k] * c[k + 1];
        r.z += wt[k] * c[k + 2];
        r.w += wt[k] * c[k + 3];
    }
    return r;
}

// Gather-aggregate one node's neighborhood (self + CSR), fp16 in, fp32 acc.
__device__ __forceinline__ float4 aggregate(const __half* __restrict__ hin,
                                            int n, int lane) {
    int beg = g_start[n], end = g_start[n + 1];
    size_t lo = (size_t)lane * 4;
    float4 acc = make_float4(0.f, 0.f, 0.f, 0.f);
    acc_u2(acc, *(const uint2*)(hin + (size_t)n * TT + lo));   // self loop
    int k = beg;
    for (; k + 4 <= end; k += 4) {
        int s0 = g_csr[k], s1 = g_csr[k + 1], s2 = g_csr[k + 2], s3 = g_csr[k + 3];
        uint2 u0 = *(const uint2*)(hin + (size_t)s0 * TT + lo);
        uint2 u1 = *(const uint2*)(hin + (size_t)s1 * TT + lo);
        uint2 u2 = *(const uint2*)(hin + (size_t)s2 * TT + lo);
        uint2 u3 = *(const uint2*)(hin + (size_t)s3 * TT + lo);
        acc_u2(acc, u0); acc_u2(acc, u1); acc_u2(acc, u2); acc_u2(acc, u3);
    }
    for (; k < end; k++)
        acc_u2(acc, *(const uint2*)(hin + (size_t)g_csr[k] * TT + lo));
    return acc;
}

// Layer-0 conv: warp per node, fp32 in -> fp16 out.
__global__ void conv0_kernel(const float* __restrict__ xin,
                             const float* __restrict__ cw,
                             const float* __restrict__ cb,
                             __half* __restrict__ h) {
    int n = blockIdx.x * 8 + (threadIdx.x >> 5);
    int lane = threadIdx.x & 31;
    if (n >= NV) return;
    float wt[KK];
#pragma unroll
    for (int k = 0; k < KK; k++) wt[k] = cw[k];
    float4 v = *(const float4*)(xin + (size_t)n * TT + lane * 4);
    float4 r = conv_shfl(v, wt, cb[0], lane);
    store_row(h, n, lane, r);
}

// Fused agg + mean + relu + next conv (layers 1, 2).
__global__ void agg_conv_kernel(const __half* __restrict__ hin,
                                __half* __restrict__ hout,
                                const float* __restrict__ cw,
                                const float* __restrict__ cb,
                                int layer) {
    int n = blockIdx.x * 8 + (threadIdx.x >> 5);
    int lane = threadIdx.x & 31;
    if (n >= NV) return;
    float4 acc = aggregate(hin, n, lane);
    float inv = g_inv[n];
    float4 v;
    v.x = fmaxf(acc.x * inv, 0.f);
    v.y = fmaxf(acc.y * inv, 0.f);
    v.z = fmaxf(acc.z * inv, 0.f);
    v.w = fmaxf(acc.w * inv, 0.f);
    float wt[KK];
#pragma unroll
    for (int q = 0; q < KK; q++) wt[q] = cw[layer * KK + q];
    v = conv_shfl(v, wt, cb[layer], lane);
    store_row(hout, n, lane, v);
}

__global__ void init_out_kernel(const float* __restrict__ bout,
                                float* __restrict__ out) {
    int i = threadIdx.x;
    if (i < TT * 3) out[i] = bout[i % 3];
}

// Fused final agg + mean + relu + output matvec with flat-reshape semantics:
// value of node n at time t sits at flat f = n*128+t of x.reshape(128, NV);
// contributes to out[i = f/NV, c] with weight W[c*NV + (f%NV)].
__global__ void agg_out_kernel(const __half* __restrict__ hin,
                               const float* __restrict__ W,
                               float* __restrict__ out) {
    __shared__ float sm[8][TT * 3];   // per-warp accumulator banks
    int w = threadIdx.x >> 5, lane = threadIdx.x & 31;
    for (int i = threadIdx.x; i < 8 * TT * 3; i += 256)
        ((float*)sm)[i] = 0.f;
    __syncthreads();

    int stride = gridDim.x * 8;
    for (int n = blockIdx.x * 8 + w; n < NV; n += stride) {
        float4 acc = aggregate(hin, n, lane);
        float inv = g_inv[n];
        float v[4];
        v[0] = fmaxf(acc.x * inv, 0.f);
        v[1] = fmaxf(acc.y * inv, 0.f);
        v[2] = fmaxf(acc.z * inv, 0.f);
        v[3] = fmaxf(acc.w * inv, 0.f);

        int fbase = n * TT;              // flat index of t=0
        int i0 = fbase / NV;
        int B  = (i0 + 1) * NV;
        int f  = fbase + lane * 4;
        float s0[3] = {0.f, 0.f, 0.f}, s1[3] = {0.f, 0.f, 0.f};
#pragma unroll
        for (int q = 0; q < 4; q++) {
            int fq = f + q;
            bool hi = fq >= B;
            int j = fq - (hi ? B : i0 * NV);
            float w0 = __ldg(W + j);
            float w1 = __ldg(W + NV + j);
            float w2 = __ldg(W + 2 * NV + j);
            if (hi) { s1[0] += v[q] * w0; s1[1] += v[q] * w1; s1[2] += v[q] * w2; }
            else    { s0[0] += v[q] * w0; s0[1] += v[q] * w1; s0[2] += v[q] * w2; }
        }
#pragma unroll
        for (int off = 16; off; off >>= 1) {
            s0[0] += __shfl_down_sync(~0u, s0[0], off);
            s0[1] += __shfl_down_sync(~0u, s0[1], off);
            s0[2] += __shfl_down_sync(~0u, s0[2], off);
            s1[0] += __shfl_down_sync(~0u, s1[0], off);
            s1[1] += __shfl_down_sync(~0u, s1[1], off);
            s1[2] += __shfl_down_sync(~0u, s1[2], off);
        }
        if (lane == 0) {
            sm[w][i0 * 3 + 0] += s0[0];
            sm[w][i0 * 3 + 1] += s0[1];
            sm[w][i0 * 3 + 2] += s0[2];
            if (B < fbase + TT) {
                sm[w][(i0 + 1) * 3 + 0] += s1[0];
                sm[w][(i0 + 1) * 3 + 1] += s1[1];
                sm[w][(i0 + 1) * 3 + 2] += s1[2];
            }
        }
    }
    __syncthreads();
    for (int i = threadIdx.x; i < TT * 3; i += 256) {
        float s = 0.f;
#pragma unroll
        for (int ww = 0; ww < 8; ww++) s += sm[ww][i];
        atomicAdd(&out[i], s);
    }
}

// ---------------------------------------------------------------------------
extern "C" void kernel_launch(void* const* d_in, const int* in_sizes, int n_in,
                              void* d_out, int out_size) {
    const float* x  = (const float*)d_in[0];
    const int*   ei = (const int*)  d_in[1];
    const float* cw = (const float*)d_in[2];
    const float* cb = (const float*)d_in[3];
    const float* W  = (const float*)d_in[4];
    const float* bo = (const float*)d_in[5];
    float* out = (float*)d_out;

    __half *hA, *hB;
    void* degp;
    cudaGetSymbolAddress((void**)&hA, g_hA);
    cudaGetSymbolAddress((void**)&hB, g_hB);
    cudaGetSymbolAddress(&degp, g_deg);

    // Build dst-CSR.
    cudaMemsetAsync(degp, 0, NV * sizeof(int));
    count_kernel<<<(NE / 4 + 255) / 256, 256>>>(ei);
    chunk_sum_kernel<<<NCHUNK, 1024>>>();
    chunk_scan_kernel<<<1, 128>>>();
    chunk_fill_kernel<<<NCHUNK, 1024>>>();
    fill_kernel<<<(NE / 4 + 255) / 256, 256>>>(ei);

    int gagg = (NV + 7) / 8;
    conv0_kernel<<<gagg, 256>>>(x, cw, cb, hA);
    agg_conv_kernel<<<gagg, 256>>>(hA, hB, cw, cb, 1);
    agg_conv_kernel<<<gagg, 256>>>(hB, hA, cw, cb, 2);

    init_out_kernel<<<1, TT * 3>>>(bo, out);
    agg_out_kernel<<<592, 256>>>(hA, W, out);
}

// round 10
// speedup vs baseline: 3.8574x; 1.0137x over previous
#include <cuda_runtime.h>
#include <cuda_fp16.h>
#include <cuda_bf16.h>

#define NV 100000
#define TT 128
#define NE 1600000
#define KK 9
#define NCHUNK 98          // ceil(NV/1024)

// Scratch (no allocations allowed -> __device__ globals).
__device__ __half g_hA [(size_t)NV * TT];   // fp16 ping (25.6MB)
__device__ __half g_hB [(size_t)NV * TT];   // fp16 pong (25.6MB)
__device__ float  g_inv[NV];
__device__ int    g_deg[NV];
__device__ int    g_start[NV + 1];
__device__ int    g_cursor[NV];
__device__ int    g_csr[NE];
__device__ int    g_csum[NCHUNK];

// ---------------------------------------------------------------------------
// Degree count (1 edge/thread) + out-bias init + start[NV], via GLOBAL index.
__global__ void count_kernel(const int* __restrict__ ei,
                             const float* __restrict__ bout,
                             float* __restrict__ out) {
    int e = blockIdx.x * blockDim.x + threadIdx.x;
    if (e < NE) atomicAdd(&g_deg[__ldg(ei + NE + e)], 1);
    if (e < TT * 3) out[e] = bout[e % 3];
    if (e == TT * 3) g_start[NV] = NE;
}

__global__ void chunk_sum_kernel() {
    int i = blockIdx.x * 1024 + threadIdx.x;
    int d = (i < NV) ? g_deg[i] : 0;
#pragma unroll
    for (int off = 16; off; off >>= 1) d += __shfl_down_sync(~0u, d, off);
    __shared__ int ws[32];
    int w = threadIdx.x >> 5, l = threadIdx.x & 31;
    if (l == 0) ws[w] = d;
    __syncthreads();
    if (threadIdx.x < 32) {
        int v = ws[threadIdx.x];
#pragma unroll
        for (int off = 16; off; off >>= 1) v += __shfl_down_sync(~0u, v, off);
        if (threadIdx.x == 0) g_csum[blockIdx.x] = v;
    }
}

// Per-chunk scan with inline block-offset reduction (no separate scan kernel).
__global__ void chunk_fill_kernel() {
    int t = threadIdx.x;
    int l = t & 31, w = t >> 5;
    __shared__ int ws[32];
    __shared__ int s_off;

    // Block offset = sum of csum[j] for j < blockIdx.x (blockIdx.x <= 97).
    {
        int v = (t < blockIdx.x) ? g_csum[t] : 0;
#pragma unroll
        for (int off = 16; off; off >>= 1) v += __shfl_down_sync(~0u, v, off);
        if (l == 0) ws[w] = v;
        __syncthreads();
        if (t < 32) {
            int v2 = ws[t];
#pragma unroll
            for (int off = 16; off; off >>= 1) v2 += __shfl_down_sync(~0u, v2, off);
            if (t == 0) s_off = v2;
        }
        __syncthreads();
    }

    int i = blockIdx.x * 1024 + t;
    int d = (i < NV) ? g_deg[i] : 0;
    int s = d;
#pragma unroll
    for (int off = 1; off < 32; off <<= 1) {
        int u = __shfl_up_sync(~0u, s, off);
        if (l >= off) s += u;
    }
    __syncthreads();                 // ws reuse barrier
    if (l == 31) ws[w] = s;
    __syncthreads();
    if (t < 32) {
        int v = ws[t];
#pragma unroll
        for (int off = 1; off < 32; off <<= 1) {
            int u = __shfl_up_sync(~0u, v, off);
            if (t >= off) v += u;
        }
        ws[t] = v;
    }
    __syncthreads();
    int incl = s + (w ? ws[w - 1] : 0) + s_off;
    if (i < NV) {
        int st = incl - d;
        g_start[i]  = st;
        g_cursor[i] = st;
        g_inv[i]    = 1.0f / (float)(d + 1);
    }
}

// CSR fill: 1 edge/thread (single atomic chain, latency hidden by waves).
__global__ void fill_kernel(const int* __restrict__ ei) {
    int e = blockIdx.x * blockDim.x + threadIdx.x;
    if (e < NE) {
        int s = __ldg(ei + e);
        int d = __ldg(ei + NE + e);
        g_csr[atomicAdd(&g_cursor[d], 1)] = s;
    }
}

// ---------------------------------------------------------------------------
// fp16 row helpers: lane l holds t = 4l..4l+3 (8 bytes per lane).
__device__ __forceinline__ void acc_u2(float4& acc, uint2 u) {
    float2 a = __half22float2(*reinterpret_cast<__half2*>(&u.x));
    float2 b = __half22float2(*reinterpret_cast<__half2*>(&u.y));
    acc.x += a.x; acc.y += a.y; acc.z += b.x; acc.w += b.y;
}

__device__ __forceinline__ void store_row(__half* __restrict__ h, int n, int lane,
                                          float4 v) {
    uint2 u;
    *reinterpret_cast<__half2*>(&u.x) = __floats2half2_rn(v.x, v.y);
    *reinterpret_cast<__half2*>(&u.y) = __floats2half2_rn(v.z, v.w);
    *(uint2*)(h + (size_t)n * TT + lane * 4) = u;
}

// Register conv1d (K=9) across a warp-held row (fp32).
__device__ __forceinline__ float4 conv_shfl(float4 v, const float* __restrict__ wt,
                                            float bias, int lane) {
    float c[12];
    c[4] = v.x; c[5] = v.y; c[6] = v.z; c[7] = v.w;
    c[0] = __shfl_up_sync(~0u, v.x, 1);
    c[1] = __shfl_up_sync(~0u, v.y, 1);
    c[2] = __shfl_up_sync(~0u, v.z, 1);
    c[3] = __shfl_up_sync(~0u, v.w, 1);
    c[8]  = __shfl_down_sync(~0u, v.x, 1);
    c[9]  = __shfl_down_sync(~0u, v.y, 1);
    c[10] = __shfl_down_sync(~0u, v.z, 1);
    c[11] = __shfl_down_sync(~0u, v.w, 1);
    if (lane == 0)  { c[0] = c[1] = c[2] = c[3] = 0.f; }
    if (lane == 31) { c[8] = c[9] = c[10] = c[11] = 0.f; }
    float4 r;
    r.x = bias; r.y = bias; r.z = bias; r.w = bias;
#pragma unroll
    for (int k = 0; k < KK; k++) {
        r.x += wt[k] * c[k];
        r.y += wt[k] * c[k + 1];
        r.z += wt[k] * c[k + 2];
        r.w += wt[k] * c[k + 3];
    }
    return r;
}

// Gather-aggregate one node's neighborhood (self + CSR), fp16 in, fp32 acc.
__device__ __forceinline__ float4 aggregate(const __half* __restrict__ hin,
                                            int n, int lane) {
    int beg = g_start[n], end = g_start[n + 1];
    size_t lo = (size_t)lane * 4;
    float4 acc = make_float4(0.f, 0.f, 0.f, 0.f);
    acc_u2(acc, *(const uint2*)(hin + (size_t)n * TT + lo));   // self loop
    int k = beg;
    for (; k + 4 <= end; k += 4) {
        int s0 = g_csr[k], s1 = g_csr[k + 1], s2 = g_csr[k + 2], s3 = g_csr[k + 3];
        uint2 u0 = *(const uint2*)(hin + (size_t)s0 * TT + lo);
        uint2 u1 = *(const uint2*)(hin + (size_t)s1 * TT + lo);
        uint2 u2 = *(const uint2*)(hin + (size_t)s2 * TT + lo);
        uint2 u3 = *(const uint2*)(hin + (size_t)s3 * TT + lo);
        acc_u2(acc, u0); acc_u2(acc, u1); acc_u2(acc, u2); acc_u2(acc, u3);
    }
    for (; k < end; k++)
        acc_u2(acc, *(const uint2*)(hin + (size_t)g_csr[k] * TT + lo));
    return acc;
}

// Layer-0 conv: warp per node, fp32 in -> fp16 out.
__global__ void conv0_kernel(const float* __restrict__ xin,
                             const float* __restrict__ cw,
                             const float* __restrict__ cb,
                             __half* __restrict__ h) {
    int n = blockIdx.x * 8 + (threadIdx.x >> 5);
    int lane = threadIdx.x & 31;
    if (n >= NV) return;
    float wt[KK];
#pragma unroll
    for (int k = 0; k < KK; k++) wt[k] = cw[k];
    float4 v = *(const float4*)(xin + (size_t)n * TT + lane * 4);
    float4 r = conv_shfl(v, wt, cb[0], lane);
    store_row(h, n, lane, r);
}

// Fused agg + mean + relu + next conv (layers 1, 2).
__global__ void agg_conv_kernel(const __half* __restrict__ hin,
                                __half* __restrict__ hout,
                                const float* __restrict__ cw,
                                const float* __restrict__ cb,
                                int layer) {
    int n = blockIdx.x * 8 + (threadIdx.x >> 5);
    int lane = threadIdx.x & 31;
    if (n >= NV) return;
    float4 acc = aggregate(hin, n, lane);
    float inv = g_inv[n];
    float4 v;
    v.x = fmaxf(acc.x * inv, 0.f);
    v.y = fmaxf(acc.y * inv, 0.f);
    v.z = fmaxf(acc.z * inv, 0.f);
    v.w = fmaxf(acc.w * inv, 0.f);
    float wt[KK];
#pragma unroll
    for (int q = 0; q < KK; q++) wt[q] = cw[layer * KK + q];
    v = conv_shfl(v, wt, cb[layer], lane);
    store_row(hout, n, lane, v);
}

// Fused final agg + mean + relu + output matvec with flat-reshape semantics:
// value of node n at time t sits at flat f = n*128+t of x.reshape(128, NV);
// contributes to out[i = f/NV, c] with weight W[c*NV + (f%NV)].
__global__ void agg_out_kernel(const __half* __restrict__ hin,
                               const float* __restrict__ W,
                               float* __restrict__ out) {
    __shared__ float sm[8][TT * 3];   // per-warp accumulator banks
    int w = threadIdx.x >> 5, lane = threadIdx.x & 31;
    for (int i = threadIdx.x; i < 8 * TT * 3; i += 256)
        ((float*)sm)[i] = 0.f;
    __syncthreads();

    int stride = gridDim.x * 8;
    for (int n = blockIdx.x * 8 + w; n < NV; n += stride) {
        float4 acc = aggregate(hin, n, lane);
        float inv = g_inv[n];
        float v[4];
        v[0] = fmaxf(acc.x * inv, 0.f);
        v[1] = fmaxf(acc.y * inv, 0.f);
        v[2] = fmaxf(acc.z * inv, 0.f);
        v[3] = fmaxf(acc.w * inv, 0.f);

        int fbase = n * TT;              // flat index of t=0
        int i0 = fbase / NV;
        int B  = (i0 + 1) * NV;
        int f  = fbase + lane * 4;
        float s0[3] = {0.f, 0.f, 0.f}, s1[3] = {0.f, 0.f, 0.f};
#pragma unroll
        for (int q = 0; q < 4; q++) {
            int fq = f + q;
            bool hi = fq >= B;
            int j = fq - (hi ? B : i0 * NV);
            float w0 = __ldg(W + j);
            float w1 = __ldg(W + NV + j);
            float w2 = __ldg(W + 2 * NV + j);
            if (hi) { s1[0] += v[q] * w0; s1[1] += v[q] * w1; s1[2] += v[q] * w2; }
            else    { s0[0] += v[q] * w0; s0[1] += v[q] * w1; s0[2] += v[q] * w2; }
        }
#pragma unroll
        for (int off = 16; off; off >>= 1) {
            s0[0] += __shfl_down_sync(~0u, s0[0], off);
            s0[1] += __shfl_down_sync(~0u, s0[1], off);
            s0[2] += __shfl_down_sync(~0u, s0[2], off);
            s1[0] += __shfl_down_sync(~0u, s1[0], off);
            s1[1] += __shfl_down_sync(~0u, s1[1], off);
            s1[2] += __shfl_down_sync(~0u, s1[2], off);
        }
        if (lane == 0) {
            sm[w][i0 * 3 + 0] += s0[0];
            sm[w][i0 * 3 + 1] += s0[1];
            sm[w][i0 * 3 + 2] += s0[2];
            if (B < fbase + TT) {
                sm[w][(i0 + 1) * 3 + 0] += s1[0];
                sm[w][(i0 + 1) * 3 + 1] += s1[1];
                sm[w][(i0 + 1) * 3 + 2] += s1[2];
            }
        }
    }
    __syncthreads();
    for (int i = threadIdx.x; i < TT * 3; i += 256) {
        float s = 0.f;
#pragma unroll
        for (int ww = 0; ww < 8; ww++) s += sm[ww][i];
        atomicAdd(&out[i], s);
    }
}

// ---------------------------------------------------------------------------
extern "C" void kernel_launch(void* const* d_in, const int* in_sizes, int n_in,
                              void* d_out, int out_size) {
    const float* x  = (const float*)d_in[0];
    const int*   ei = (const int*)  d_in[1];
    const float* cw = (const float*)d_in[2];
    const float* cb = (const float*)d_in[3];
    const float* W  = (const float*)d_in[4];
    const float* bo = (const float*)d_in[5];
    float* out = (float*)d_out;

    __half *hA, *hB;
    void* degp;
    cudaGetSymbolAddress((void**)&hA, g_hA);
    cudaGetSymbolAddress((void**)&hB, g_hB);
    cudaGetSymbolAddress(&degp, g_deg);

    // Build dst-CSR (count also inits out-bias and start[NV]).
    cudaMemsetAsync(degp, 0, NV * sizeof(int));
    count_kernel<<<(NE + 255) / 256, 256>>>(ei, bo, out);
    chunk_sum_kernel<<<NCHUNK, 1024>>>();
    chunk_fill_kernel<<<NCHUNK, 1024>>>();
    fill_kernel<<<(NE + 255) / 256, 256>>>(ei);

    int gagg = (NV + 7) / 8;
    conv0_kernel<<<gagg, 256>>>(x, cw, cb, hA);
    agg_conv_kernel<<<gagg, 256>>>(hA, hB, cw, cb, 1);
    agg_conv_kernel<<<gagg, 256>>>(hB, hA, cw, cb, 2);
    agg_out_kernel<<<592, 256>>>(hA, W, out);
}

// round 11
// speedup vs baseline: 3.9236x; 1.0172x over previous
#include <cuda_runtime.h>
#include <cuda_fp16.h>
#include <cuda_bf16.h>

#define NV 100000
#define TT 128
#define NE 1600000
#define KK 9
#define NCHUNK 98           // ceil(NV/1024)
#define CNT_BLK 6250        // NE/256
#define CONV_BLK 12500      // NV/8
#define ZERO_BLK 391        // ceil(NV/256)

// Scratch (no allocations allowed -> __device__ globals, zero-initialized).
__device__ __half g_hA [(size_t)NV * TT];   // fp16 ping (25.6MB)
__device__ __half g_hB [(size_t)NV * TT];   // fp16 pong (25.6MB)
__device__ float  g_inv[NV];
__device__ int    g_deg[NV];                // zero at load; re-zeroed each call
__device__ int    g_start[NV + 1];
__device__ int    g_cursor[NV];
__device__ int    g_csr[NE];
__device__ int    g_csum[NCHUNK];

// ---------------------------------------------------------------------------
// fp16 row helpers: lane l holds t = 4l..4l+3 (8 bytes per lane).
__device__ __forceinline__ void acc_u2(float4& acc, uint2 u) {
    float2 a = __half22float2(*reinterpret_cast<__half2*>(&u.x));
    float2 b = __half22float2(*reinterpret_cast<__half2*>(&u.y));
    acc.x += a.x; acc.y += a.y; acc.z += b.x; acc.w += b.y;
}

__device__ __forceinline__ void store_row(__half* __restrict__ h, int n, int lane,
                                          float4 v) {
    uint2 u;
    *reinterpret_cast<__half2*>(&u.x) = __floats2half2_rn(v.x, v.y);
    *reinterpret_cast<__half2*>(&u.y) = __floats2half2_rn(v.z, v.w);
    *(uint2*)(h + (size_t)n * TT + lane * 4) = u;
}

// Register conv1d (K=9) across a warp-held row (fp32).
__device__ __forceinline__ float4 conv_shfl(float4 v, const float* __restrict__ wt,
                                            float bias, int lane) {
    float c[12];
    c[4] = v.x; c[5] = v.y; c[6] = v.z; c[7] = v.w;
    c[0] = __shfl_up_sync(~0u, v.x, 1);
    c[1] = __shfl_up_sync(~0u, v.y, 1);
    c[2] = __shfl_up_sync(~0u, v.z, 1);
    c[3] = __shfl_up_sync(~0u, v.w, 1);
    c[8]  = __shfl_down_sync(~0u, v.x, 1);
    c[9]  = __shfl_down_sync(~0u, v.y, 1);
    c[10] = __shfl_down_sync(~0u, v.z, 1);
    c[11] = __shfl_down_sync(~0u, v.w, 1);
    if (lane == 0)  { c[0] = c[1] = c[2] = c[3] = 0.f; }
    if (lane == 31) { c[8] = c[9] = c[10] = c[11] = 0.f; }
    float4 r;
    r.x = bias; r.y = bias; r.z = bias; r.w = bias;
#pragma unroll
    for (int k = 0; k < KK; k++) {
        r.x += wt[k] * c[k];
        r.y += wt[k] * c[k + 1];
        r.z += wt[k] * c[k + 2];
        r.w += wt[k] * c[k + 3];
    }
    return r;
}

// ---------------------------------------------------------------------------
// Fused: degree count (blocks 0..CNT_BLK-1) + layer-0 conv (remaining blocks).
// Independent work sharing one launch -> atomics overlap with DRAM streaming.
__global__ void count_conv0_kernel(const int* __restrict__ ei,
                                   const float* __restrict__ bout,
                                   float* __restrict__ out,
                                   const float* __restrict__ xin,
                                   const float* __restrict__ cw,
                                   const float* __restrict__ cb,
                                   __half* __restrict__ h) {
    int b = blockIdx.x;
    if (b < CNT_BLK) {
        int e = b * 256 + threadIdx.x;
        if (e < NE) atomicAdd(&g_deg[__ldg(ei + NE + e)], 1);
        if (e < TT * 3) out[e] = bout[e % 3];
        if (e == TT * 3) g_start[NV] = NE;
    } else {
        int n = (b - CNT_BLK) * 8 + (threadIdx.x >> 5);
        int lane = threadIdx.x & 31;
        if (n >= NV) return;
        float wt[KK];
#pragma unroll
        for (int k = 0; k < KK; k++) wt[k] = cw[k];
        float4 v = *(const float4*)(xin + (size_t)n * TT + lane * 4);
        float4 r = conv_shfl(v, wt, cb[0], lane);
        store_row(h, n, lane, r);
    }
}

__global__ void chunk_sum_kernel() {
    int i = blockIdx.x * 1024 + threadIdx.x;
    int d = (i < NV) ? g_deg[i] : 0;
#pragma unroll
    for (int off = 16; off; off >>= 1) d += __shfl_down_sync(~0u, d, off);
    __shared__ int ws[32];
    int w = threadIdx.x >> 5, l = threadIdx.x & 31;
    if (l == 0) ws[w] = d;
    __syncthreads();
    if (threadIdx.x < 32) {
        int v = ws[threadIdx.x];
#pragma unroll
        for (int off = 16; off; off >>= 1) v += __shfl_down_sync(~0u, v, off);
        if (threadIdx.x == 0) g_csum[blockIdx.x] = v;
    }
}

// Per-chunk scan with inline block-offset reduction.
__global__ void chunk_fill_kernel() {
    int t = threadIdx.x;
    int l = t & 31, w = t >> 5;
    __shared__ int ws[32];
    __shared__ int s_off;

    {   // Block offset = sum of csum[j] for j < blockIdx.x (<= 97).
        int v = (t < blockIdx.x) ? g_csum[t] : 0;
#pragma unroll
        for (int off = 16; off; off >>= 1) v += __shfl_down_sync(~0u, v, off);
        if (l == 0) ws[w] = v;
        __syncthreads();
        if (t < 32) {
            int v2 = ws[t];
#pragma unroll
            for (int off = 16; off; off >>= 1) v2 += __shfl_down_sync(~0u, v2, off);
            if (t == 0) s_off = v2;
        }
        __syncthreads();
    }

    int i = blockIdx.x * 1024 + t;
    int d = (i < NV) ? g_deg[i] : 0;
    int s = d;
#pragma unroll
    for (int off = 1; off < 32; off <<= 1) {
        int u = __shfl_up_sync(~0u, s, off);
        if (l >= off) s += u;
    }
    __syncthreads();                 // ws reuse barrier
    if (l == 31) ws[w] = s;
    __syncthreads();
    if (t < 32) {
        int v = ws[t];
#pragma unroll
        for (int off = 1; off < 32; off <<= 1) {
            int u = __shfl_up_sync(~0u, v, off);
            if (t >= off) v += u;
        }
        ws[t] = v;
    }
    __syncthreads();
    int incl = s + (w ? ws[w - 1] : 0) + s_off;
    if (i < NV) {
        int st = incl - d;
        g_start[i]  = st;
        g_cursor[i] = st;
        g_inv[i]    = 1.0f / (float)(d + 1);
    }
}

// CSR fill (blocks 0..CNT_BLK-1) + g_deg re-zero for next replay (rest).
// deg's last reader is chunk_fill_kernel (already done) -> no race.
__global__ void fill_kernel(const int* __restrict__ ei) {
    int b = blockIdx.x;
    if (b < CNT_BLK) {
        int e = b * 256 + threadIdx.x;
        if (e < NE) {
            int s = __ldg(ei + e);
            int d = __ldg(ei + NE + e);
            g_csr[atomicAdd(&g_cursor[d], 1)] = s;
        }
    } else {
        int i = (b - CNT_BLK) * 256 + threadIdx.x;
        if (i < NV) g_deg[i] = 0;
    }
}

// ---------------------------------------------------------------------------
// Gather-aggregate one node's neighborhood (self + CSR), fp16 in, fp32 acc.
__device__ __forceinline__ float4 aggregate(const __half* __restrict__ hin,
                                            int n, int lane) {
    int beg = g_start[n], end = g_start[n + 1];
    size_t lo = (size_t)lane * 4;
    float4 acc = make_float4(0.f, 0.f, 0.f, 0.f);
    acc_u2(acc, *(const uint2*)(hin + (size_t)n * TT + lo));   // self loop
    int k = beg;
    for (; k + 4 <= end; k += 4) {
        int s0 = g_csr[k], s1 = g_csr[k + 1], s2 = g_csr[k + 2], s3 = g_csr[k + 3];
        uint2 u0 = *(const uint2*)(hin + (size_t)s0 * TT + lo);
        uint2 u1 = *(const uint2*)(hin + (size_t)s1 * TT + lo);
        uint2 u2 = *(const uint2*)(hin + (size_t)s2 * TT + lo);
        uint2 u3 = *(const uint2*)(hin + (size_t)s3 * TT + lo);
        acc_u2(acc, u0); acc_u2(acc, u1); acc_u2(acc, u2); acc_u2(acc, u3);
    }
    for (; k < end; k++)
        acc_u2(acc, *(const uint2*)(hin + (size_t)g_csr[k] * TT + lo));
    return acc;
}

// Fused agg + mean + relu + next conv (layers 1, 2).
__global__ void agg_conv_kernel(const __half* __restrict__ hin,
                                __half* __restrict__ hout,
                                const float* __restrict__ cw,
                                const float* __restrict__ cb,
                                int layer) {
    int n = blockIdx.x * 8 + (threadIdx.x >> 5);
    int lane = threadIdx.x & 31;
    if (n >= NV) return;
    float4 acc = aggregate(hin, n, lane);
    float inv = g_inv[n];
    float4 v;
    v.x = fmaxf(acc.x * inv, 0.f);
    v.y = fmaxf(acc.y * inv, 0.f);
    v.z = fmaxf(acc.z * inv, 0.f);
    v.w = fmaxf(acc.w * inv, 0.f);
    float wt[KK];
#pragma unroll
    for (int q = 0; q < KK; q++) wt[q] = cw[layer * KK + q];
    v = conv_shfl(v, wt, cb[layer], lane);
    store_row(hout, n, lane, v);
}

// Fused final agg + mean + relu + output matvec with flat-reshape semantics:
// value of node n at time t sits at flat f = n*128+t of x.reshape(128, NV);
// contributes to out[i = f/NV, c] with weight W[c*NV + (f%NV)].
__global__ void agg_out_kernel(const __half* __restrict__ hin,
                               const float* __restrict__ W,
                               float* __restrict__ out) {
    __shared__ float sm[8][TT * 3];   // per-warp accumulator banks
    int w = threadIdx.x >> 5, lane = threadIdx.x & 31;
    for (int i = threadIdx.x; i < 8 * TT * 3; i += 256)
        ((float*)sm)[i] = 0.f;
    __syncthreads();

    int stride = gridDim.x * 8;
    for (int n = blockIdx.x * 8 + w; n < NV; n += stride) {
        float4 acc = aggregate(hin, n, lane);
        float inv = g_inv[n];
        float v[4];
        v[0] = fmaxf(acc.x * inv, 0.f);
        v[1] = fmaxf(acc.y * inv, 0.f);
        v[2] = fmaxf(acc.z * inv, 0.f);
        v[3] = fmaxf(acc.w * inv, 0.f);

        int fbase = n * TT;              // flat index of t=0
        int i0 = fbase / NV;
        int B  = (i0 + 1) * NV;
        int f  = fbase + lane * 4;
        float s0[3] = {0.f, 0.f, 0.f}, s1[3] = {0.f, 0.f, 0.f};
#pragma unroll
        for (int q = 0; q < 4; q++) {
            int fq = f + q;
            bool hi = fq >= B;
            int j = fq - (hi ? B : i0 * NV);
            float w0 = __ldg(W + j);
            float w1 = __ldg(W + NV + j);
            float w2 = __ldg(W + 2 * NV + j);
            if (hi) { s1[0] += v[q] * w0; s1[1] += v[q] * w1; s1[2] += v[q] * w2; }
            else    { s0[0] += v[q] * w0; s0[1] += v[q] * w1; s0[2] += v[q] * w2; }
        }
#pragma unroll
        for (int off = 16; off; off >>= 1) {
            s0[0] += __shfl_down_sync(~0u, s0[0], off);
            s0[1] += __shfl_down_sync(~0u, s0[1], off);
            s0[2] += __shfl_down_sync(~0u, s0[2], off);
            s1[0] += __shfl_down_sync(~0u, s1[0], off);
            s1[1] += __shfl_down_sync(~0u, s1[1], off);
            s1[2] += __shfl_down_sync(~0u, s1[2], off);
        }
        if (lane == 0) {
            sm[w][i0 * 3 + 0] += s0[0];
            sm[w][i0 * 3 + 1] += s0[1];
            sm[w][i0 * 3 + 2] += s0[2];
            if (B < fbase + TT) {
                sm[w][(i0 + 1) * 3 + 0] += s1[0];
                sm[w][(i0 + 1) * 3 + 1] += s1[1];
                sm[w][(i0 + 1) * 3 + 2] += s1[2];
            }
        }
    }
    __syncthreads();
    for (int i = threadIdx.x; i < TT * 3; i += 256) {
        float s = 0.f;
#pragma unroll
        for (int ww = 0; ww < 8; ww++) s += sm[ww][i];
        atomicAdd(&out[i], s);
    }
}

// ---------------------------------------------------------------------------
extern "C" void kernel_launch(void* const* d_in, const int* in_sizes, int n_in,
                              void* d_out, int out_size) {
    const float* x  = (const float*)d_in[0];
    const int*   ei = (const int*)  d_in[1];
    const float* cw = (const float*)d_in[2];
    const float* cb = (const float*)d_in[3];
    const float* W  = (const float*)d_in[4];
    const float* bo = (const float*)d_in[5];
    float* out = (float*)d_out;

    __half *hA, *hB;
    cudaGetSymbolAddress((void**)&hA, g_hA);
    cudaGetSymbolAddress((void**)&hB, g_hB);

    // CSR build; g_deg is zero (load-time init on call 1, re-zeroed by
    // fill_kernel's tail blocks on every call for graph replays).
    count_conv0_kernel<<<CNT_BLK + CONV_BLK, 256>>>(ei, bo, out, x, cw, cb, hA);
    chunk_sum_kernel<<<NCHUNK, 1024>>>();
    chunk_fill_kernel<<<NCHUNK, 1024>>>();
    fill_kernel<<<CNT_BLK + ZERO_BLK, 256>>>(ei);

    int gagg = (NV + 7) / 8;
    agg_conv_kernel<<<gagg, 256>>>(hA, hB, cw, cb, 1);
    agg_conv_kernel<<<gagg, 256>>>(hB, hA, cw, cb, 2);
    agg_out_kernel<<<592, 256>>>(hA, W, out);
}

// round 12
// speedup vs baseline: 4.1353x; 1.0540x over previous
#include <cuda_runtime.h>
#include <cuda_fp16.h>
#include <cuda_bf16.h>

#define NV 100000
#define TT 128
#define NE 1600000
#define KK 9
#define NCHUNK 98           // ceil(NV/1024)
#define CNT_BLK 6250        // NE/256
#define CONV_BLK 12500      // NV/8
#define ZERO_BLK 391        // ceil(NV/256)

// Scratch (no allocations allowed -> __device__ globals, zero-initialized).
__device__ __half g_hA [(size_t)NV * TT];   // fp16 ping (25.6MB)
__device__ __half g_hB [(size_t)NV * TT];   // fp16 pong (25.6MB)
__device__ float  g_inv[NV];
__device__ int    g_deg[NV];                // zero at load; re-zeroed each call
__device__ int    g_start[NV + 1];
__device__ int    g_pos[NE];                // per-edge rank within its dst node
__device__ int    g_csr[NE];
__device__ int    g_csum[NCHUNK];

// ---------------------------------------------------------------------------
// fp16 row helpers: lane l holds t = 4l..4l+3 (8 bytes per lane).
__device__ __forceinline__ void acc_u2(float4& acc, uint2 u) {
    float2 a = __half22float2(*reinterpret_cast<__half2*>(&u.x));
    float2 b = __half22float2(*reinterpret_cast<__half2*>(&u.y));
    acc.x += a.x; acc.y += a.y; acc.z += b.x; acc.w += b.y;
}

__device__ __forceinline__ void store_row(__half* __restrict__ h, int n, int lane,
                                          float4 v) {
    uint2 u;
    *reinterpret_cast<__half2*>(&u.x) = __floats2half2_rn(v.x, v.y);
    *reinterpret_cast<__half2*>(&u.y) = __floats2half2_rn(v.z, v.w);
    *(uint2*)(h + (size_t)n * TT + lane * 4) = u;
}

// Register conv1d (K=9) across a warp-held row (fp32).
__device__ __forceinline__ float4 conv_shfl(float4 v, const float* __restrict__ wt,
                                            float bias, int lane) {
    float c[12];
    c[4] = v.x; c[5] = v.y; c[6] = v.z; c[7] = v.w;
    c[0] = __shfl_up_sync(~0u, v.x, 1);
    c[1] = __shfl_up_sync(~0u, v.y, 1);
    c[2] = __shfl_up_sync(~0u, v.z, 1);
    c[3] = __shfl_up_sync(~0u, v.w, 1);
    c[8]  = __shfl_down_sync(~0u, v.x, 1);
    c[9]  = __shfl_down_sync(~0u, v.y, 1);
    c[10] = __shfl_down_sync(~0u, v.z, 1);
    c[11] = __shfl_down_sync(~0u, v.w, 1);
    if (lane == 0)  { c[0] = c[1] = c[2] = c[3] = 0.f; }
    if (lane == 31) { c[8] = c[9] = c[10] = c[11] = 0.f; }
    float4 r;
    r.x = bias; r.y = bias; r.z = bias; r.w = bias;
#pragma unroll
    for (int k = 0; k < KK; k++) {
        r.x += wt[k] * c[k];
        r.y += wt[k] * c[k + 1];
        r.z += wt[k] * c[k + 2];
        r.w += wt[k] * c[k + 3];
    }
    return r;
}

// ---------------------------------------------------------------------------
// Fused: degree count + per-edge rank capture (blocks 0..CNT_BLK-1) +
// layer-0 conv (remaining blocks). Independent work sharing one launch.
__global__ void count_conv0_kernel(const int* __restrict__ ei,
                                   const float* __restrict__ bout,
                                   float* __restrict__ out,
                                   const float* __restrict__ xin,
                                   const float* __restrict__ cw,
                                   const float* __restrict__ cb,
                                   __half* __restrict__ h) {
    int b = blockIdx.x;
    if (b < CNT_BLK) {
        int e = b * 256 + threadIdx.x;
        if (e < NE) g_pos[e] = atomicAdd(&g_deg[__ldg(ei + NE + e)], 1);
        if (e < TT * 3) out[e] = bout[e % 3];
        if (e == TT * 3) g_start[NV] = NE;
    } else {
        int n = (b - CNT_BLK) * 8 + (threadIdx.x >> 5);
        int lane = threadIdx.x & 31;
        if (n >= NV) return;
        float wt[KK];
#pragma unroll
        for (int k = 0; k < KK; k++) wt[k] = cw[k];
        float4 v = *(const float4*)(xin + (size_t)n * TT + lane * 4);
        float4 r = conv_shfl(v, wt, cb[0], lane);
        store_row(h, n, lane, r);
    }
}

__global__ void chunk_sum_kernel() {
    int i = blockIdx.x * 1024 + threadIdx.x;
    int d = (i < NV) ? g_deg[i] : 0;
#pragma unroll
    for (int off = 16; off; off >>= 1) d += __shfl_down_sync(~0u, d, off);
    __shared__ int ws[32];
    int w = threadIdx.x >> 5, l = threadIdx.x & 31;
    if (l == 0) ws[w] = d;
    __syncthreads();
    if (threadIdx.x < 32) {
        int v = ws[threadIdx.x];
#pragma unroll
        for (int off = 16; off; off >>= 1) v += __shfl_down_sync(~0u, v, off);
        if (threadIdx.x == 0) g_csum[blockIdx.x] = v;
    }
}

// Per-chunk scan with inline block-offset reduction.
__global__ void chunk_fill_kernel() {
    int t = threadIdx.x;
    int l = t & 31, w = t >> 5;
    __shared__ int ws[32];
    __shared__ int s_off;

    {   // Block offset = sum of csum[j] for j < blockIdx.x (<= 97).
        int v = (t < blockIdx.x) ? g_csum[t] : 0;
#pragma unroll
        for (int off = 16; off; off >>= 1) v += __shfl_down_sync(~0u, v, off);
        if (l == 0) ws[w] = v;
        __syncthreads();
        if (t < 32) {
            int v2 = ws[t];
#pragma unroll
            for (int off = 16; off; off >>= 1) v2 += __shfl_down_sync(~0u, v2, off);
            if (t == 0) s_off = v2;
        }
        __syncthreads();
    }

    int i = blockIdx.x * 1024 + t;
    int d = (i < NV) ? g_deg[i] : 0;
    int s = d;
#pragma unroll
    for (int off = 1; off < 32; off <<= 1) {
        int u = __shfl_up_sync(~0u, s, off);
        if (l >= off) s += u;
    }
    __syncthreads();                 // ws reuse barrier
    if (l == 31) ws[w] = s;
    __syncthreads();
    if (t < 32) {
        int v = ws[t];
#pragma unroll
        for (int off = 1; off < 32; off <<= 1) {
            int u = __shfl_up_sync(~0u, v, off);
            if (t >= off) v += u;
        }
        ws[t] = v;
    }
    __syncthreads();
    int incl = s + (w ? ws[w - 1] : 0) + s_off;
    if (i < NV) {
        g_start[i] = incl - d;
        g_inv[i]   = 1.0f / (float)(d + 1);
    }
}

// CSR fill, ATOMIC-FREE: slot = start[dst] + precomputed rank. Tail blocks
// re-zero g_deg for the next graph replay (its last reader, chunk_fill, done).
__global__ void fill_kernel(const int* __restrict__ ei) {
    int b = blockIdx.x;
    if (b < CNT_BLK) {
        int e = b * 256 + threadIdx.x;
        if (e < NE) {
            int s = __ldg(ei + e);
            int d = __ldg(ei + NE + e);
            g_csr[g_start[d] + g_pos[e]] = s;
        }
    } else {
        int i = (b - CNT_BLK) * 256 + threadIdx.x;
        if (i < NV) g_deg[i] = 0;
    }
}

// ---------------------------------------------------------------------------
// Gather-aggregate one node's neighborhood (self + CSR), fp16 in, fp32 acc.
__device__ __forceinline__ float4 aggregate(const __half* __restrict__ hin,
                                            int n, int lane) {
    int beg = g_start[n], end = g_start[n + 1];
    size_t lo = (size_t)lane * 4;
    float4 acc = make_float4(0.f, 0.f, 0.f, 0.f);
    acc_u2(acc, *(const uint2*)(hin + (size_t)n * TT + lo));   // self loop
    int k = beg;
    for (; k + 4 <= end; k += 4) {
        int s0 = g_csr[k], s1 = g_csr[k + 1], s2 = g_csr[k + 2], s3 = g_csr[k + 3];
        uint2 u0 = *(const uint2*)(hin + (size_t)s0 * TT + lo);
        uint2 u1 = *(const uint2*)(hin + (size_t)s1 * TT + lo);
        uint2 u2 = *(const uint2*)(hin + (size_t)s2 * TT + lo);
        uint2 u3 = *(const uint2*)(hin + (size_t)s3 * TT + lo);
        acc_u2(acc, u0); acc_u2(acc, u1); acc_u2(acc, u2); acc_u2(acc, u3);
    }
    for (; k < end; k++)
        acc_u2(acc, *(const uint2*)(hin + (size_t)g_csr[k] * TT + lo));
    return acc;
}

// Fused agg + mean + relu + next conv (layers 1, 2).
__global__ void agg_conv_kernel(const __half* __restrict__ hin,
                                __half* __restrict__ hout,
                                const float* __restrict__ cw,
                                const float* __restrict__ cb,
                                int layer) {
    int n = blockIdx.x * 8 + (threadIdx.x >> 5);
    int lane = threadIdx.x & 31;
    if (n >= NV) return;
    float4 acc = aggregate(hin, n, lane);
    float inv = g_inv[n];
    float4 v;
    v.x = fmaxf(acc.x * inv, 0.f);
    v.y = fmaxf(acc.y * inv, 0.f);
    v.z = fmaxf(acc.z * inv, 0.f);
    v.w = fmaxf(acc.w * inv, 0.f);
    float wt[KK];
#pragma unroll
    for (int q = 0; q < KK; q++) wt[q] = cw[layer * KK + q];
    v = conv_shfl(v, wt, cb[layer], lane);
    store_row(hout, n, lane, v);
}

// Fused final agg + mean + relu + output matvec with flat-reshape semantics:
// value of node n at time t sits at flat f = n*128+t of x.reshape(128, NV);
// contributes to out[i = f/NV, c] with weight W[c*NV + (f%NV)].
// Fast path: whole node-row inside one output row (all but 127 nodes).
__global__ void agg_out_kernel(const __half* __restrict__ hin,
                               const float* __restrict__ W,
                               float* __restrict__ out) {
    __shared__ float sm[8][TT * 3];   // per-warp accumulator banks
    int w = threadIdx.x >> 5, lane = threadIdx.x & 31;
    for (int i = threadIdx.x; i < 8 * TT * 3; i += 256)
        ((float*)sm)[i] = 0.f;
    __syncthreads();

    int stride = gridDim.x * 8;
    for (int n = blockIdx.x * 8 + w; n < NV; n += stride) {
        float4 acc = aggregate(hin, n, lane);
        float inv = g_inv[n];
        float v[4];
        v[0] = fmaxf(acc.x * inv, 0.f);
        v[1] = fmaxf(acc.y * inv, 0.f);
        v[2] = fmaxf(acc.z * inv, 0.f);
        v[3] = fmaxf(acc.w * inv, 0.f);

        int fbase = n * TT;              // flat index of t=0
        int i0 = fbase / NV;
        int j0 = fbase - i0 * NV;        // column of t=0 (multiple of 4)

        if (j0 + TT <= NV) {
            // Fast path: single output row; coalesced float4 W loads.
            int j = j0 + lane * 4;
            float4 w0 = *(const float4*)(W + j);
            float4 w1 = *(const float4*)(W + NV + j);
            float4 w2 = *(const float4*)(W + 2 * NV + j);
            float s0 = v[0] * w0.x + v[1] * w0.y + v[2] * w0.z + v[3] * w0.w;
            float s1 = v[0] * w1.x + v[1] * w1.y + v[2] * w1.z + v[3] * w1.w;
            float s2 = v[0] * w2.x + v[1] * w2.y + v[2] * w2.z + v[3] * w2.w;
#pragma unroll
            for (int off = 16; off; off >>= 1) {
                s0 += __shfl_down_sync(~0u, s0, off);
                s1 += __shfl_down_sync(~0u, s1, off);
                s2 += __shfl_down_sync(~0u, s2, off);
            }
            if (lane == 0) {
                sm[w][i0 * 3 + 0] += s0;
                sm[w][i0 * 3 + 1] += s1;
                sm[w][i0 * 3 + 2] += s2;
            }
        } else {
            // Slow path: node-row straddles an output-row boundary.
            int B = (i0 + 1) * NV;
            int f = fbase + lane * 4;
            float s0[3] = {0.f, 0.f, 0.f}, s1[3] = {0.f, 0.f, 0.f};
#pragma unroll
            for (int q = 0; q < 4; q++) {
                int fq = f + q;
                bool hi = fq >= B;
                int j = fq - (hi ? B : i0 * NV);
                float w0 = __ldg(W + j);
                float w1 = __ldg(W + NV + j);
                float w2 = __ldg(W + 2 * NV + j);
                if (hi) { s1[0] += v[q] * w0; s1[1] += v[q] * w1; s1[2] += v[q] * w2; }
                else    { s0[0] += v[q] * w0; s0[1] += v[q] * w1; s0[2] += v[q] * w2; }
            }
#pragma unroll
            for (int off = 16; off; off >>= 1) {
                s0[0] += __shfl_down_sync(~0u, s0[0], off);
                s0[1] += __shfl_down_sync(~0u, s0[1], off);
                s0[2] += __shfl_down_sync(~0u, s0[2], off);
                s1[0] += __shfl_down_sync(~0u, s1[0], off);
                s1[1] += __shfl_down_sync(~0u, s1[1], off);
                s1[2] += __shfl_down_sync(~0u, s1[2], off);
            }
            if (lane == 0) {
                sm[w][i0 * 3 + 0] += s0[0];
                sm[w][i0 * 3 + 1] += s0[1];
                sm[w][i0 * 3 + 2] += s0[2];
                sm[w][(i0 + 1) * 3 + 0] += s1[0];
                sm[w][(i0 + 1) * 3 + 1] += s1[1];
                sm[w][(i0 + 1) * 3 + 2] += s1[2];
            }
        }
    }
    __syncthreads();
    for (int i = threadIdx.x; i < TT * 3; i += 256) {
        float s = 0.f;
#pragma unroll
        for (int ww = 0; ww < 8; ww++) s += sm[ww][i];
        atomicAdd(&out[i], s);
    }
}

// ---------------------------------------------------------------------------
extern "C" void kernel_launch(void* const* d_in, const int* in_sizes, int n_in,
                              void* d_out, int out_size) {
    const float* x  = (const float*)d_in[0];
    const int*   ei = (const int*)  d_in[1];
    const float* cw = (const float*)d_in[2];
    const float* cb = (const float*)d_in[3];
    const float* W  = (const float*)d_in[4];
    const float* bo = (const float*)d_in[5];
    float* out = (float*)d_out;

    __half *hA, *hB;
    cudaGetSymbolAddress((void**)&hA, g_hA);
    cudaGetSymbolAddress((void**)&hB, g_hB);

    // CSR build; g_deg is zero (load-time init on call 1, re-zeroed by
    // fill_kernel's tail blocks on every call for graph replays).
    count_conv0_kernel<<<CNT_BLK + CONV_BLK, 256>>>(ei, bo, out, x, cw, cb, hA);
    chunk_sum_kernel<<<NCHUNK, 1024>>>();
    chunk_fill_kernel<<<NCHUNK, 1024>>>();
    fill_kernel<<<CNT_BLK + ZERO_BLK, 256>>>(ei);

    int gagg = (NV + 7) / 8;
    agg_conv_kernel<<<gagg, 256>>>(hA, hB, cw, cb, 1);
    agg_conv_kernel<<<gagg, 256>>>(hB, hA, cw, cb, 2);
    agg_out_kernel<<<592, 256>>>(hA, W, out);
}

// round 13
// speedup vs baseline: 4.2884x; 1.0370x over previous
#include <cuda_runtime.h>
#include <cuda_fp16.h>
#include <cuda_bf16.h>

#define NV 100000
#define TT 128
#define NE 1600000
#define KK 9
#define NCHUNK 98           // ceil(NV/1024)
#define CNT_BLK 6250        // NE/256
#define CONV_BLK 12500      // NV/8
#define ZERO_BLK 391        // ceil(NV/256)

// Scratch (no allocations allowed -> __device__ globals, zero-initialized).
__device__ __half g_hA [(size_t)NV * TT];   // fp16 ping (25.6MB)
__device__ __half g_hB [(size_t)NV * TT];   // fp16 pong (25.6MB)
__device__ float  g_inv[NV];
__device__ int    g_deg[NV];                // zero at load; re-zeroed each call
__device__ int    g_start[NV + 1];
__device__ int    g_pos[NE];                // per-edge rank within its dst node
__device__ int    g_csr[NE];

// ---------------------------------------------------------------------------
// fp16 row helpers: lane l holds t = 4l..4l+3 (8 bytes per lane).
__device__ __forceinline__ void acc_u2(float4& acc, uint2 u) {
    float2 a = __half22float2(*reinterpret_cast<__half2*>(&u.x));
    float2 b = __half22float2(*reinterpret_cast<__half2*>(&u.y));
    acc.x += a.x; acc.y += a.y; acc.z += b.x; acc.w += b.y;
}

__device__ __forceinline__ void store_row(__half* __restrict__ h, int n, int lane,
                                          float4 v) {
    uint2 u;
    *reinterpret_cast<__half2*>(&u.x) = __floats2half2_rn(v.x, v.y);
    *reinterpret_cast<__half2*>(&u.y) = __floats2half2_rn(v.z, v.w);
    *(uint2*)(h + (size_t)n * TT + lane * 4) = u;
}

// Register conv1d (K=9) across a warp-held row (fp32).
__device__ __forceinline__ float4 conv_shfl(float4 v, const float* __restrict__ wt,
                                            float bias, int lane) {
    float c[12];
    c[4] = v.x; c[5] = v.y; c[6] = v.z; c[7] = v.w;
    c[0] = __shfl_up_sync(~0u, v.x, 1);
    c[1] = __shfl_up_sync(~0u, v.y, 1);
    c[2] = __shfl_up_sync(~0u, v.z, 1);
    c[3] = __shfl_up_sync(~0u, v.w, 1);
    c[8]  = __shfl_down_sync(~0u, v.x, 1);
    c[9]  = __shfl_down_sync(~0u, v.y, 1);
    c[10] = __shfl_down_sync(~0u, v.z, 1);
    c[11] = __shfl_down_sync(~0u, v.w, 1);
    if (lane == 0)  { c[0] = c[1] = c[2] = c[3] = 0.f; }
    if (lane == 31) { c[8] = c[9] = c[10] = c[11] = 0.f; }
    float4 r;
    r.x = bias; r.y = bias; r.z = bias; r.w = bias;
#pragma unroll
    for (int k = 0; k < KK; k++) {
        r.x += wt[k] * c[k];
        r.y += wt[k] * c[k + 1];
        r.z += wt[k] * c[k + 2];
        r.w += wt[k] * c[k + 3];
    }
    return r;
}

// ---------------------------------------------------------------------------
// Fused: degree count + per-edge rank capture (blocks 0..CNT_BLK-1) +
// layer-0 conv (remaining blocks). Independent work sharing one launch.
__global__ void count_conv0_kernel(const int* __restrict__ ei,
                                   const float* __restrict__ bout,
                                   float* __restrict__ out,
                                   const float* __restrict__ xin,
                                   const float* __restrict__ cw,
                                   const float* __restrict__ cb,
                                   __half* __restrict__ h) {
    int b = blockIdx.x;
    if (b < CNT_BLK) {
        int e = b * 256 + threadIdx.x;
        if (e < NE) g_pos[e] = atomicAdd(&g_deg[__ldg(ei + NE + e)], 1);
        if (e < TT * 3) out[e] = bout[e % 3];
        if (e == TT * 3) g_start[NV] = NE;
    } else {
        int n = (b - CNT_BLK) * 8 + (threadIdx.x >> 5);
        int lane = threadIdx.x & 31;
        if (n >= NV) return;
        float wt[KK];
#pragma unroll
        for (int k = 0; k < KK; k++) wt[k] = cw[k];
        float4 v = *(const float4*)(xin + (size_t)n * TT + lane * 4);
        float4 r = conv_shfl(v, wt, cb[0], lane);
        store_row(h, n, lane, r);
    }
}

// Single-kernel scan: each block directly reduces deg[0..bid*1024) for its
// prefix offset (coalesced, ~20MB total extra L2), then scans its own chunk.
__global__ void scan_kernel() {
    int t = threadIdx.x;
    int l = t & 31, w = t >> 5;
    __shared__ int ws[32];
    __shared__ int s_off;

    {   // Block offset = sum of deg[j] for j < blockIdx.x * 1024.
        int lim = blockIdx.x * 1024;
        int v = 0;
        for (int i = t; i < lim; i += 1024) v += g_deg[i];
#pragma unroll
        for (int off = 16; off; off >>= 1) v += __shfl_down_sync(~0u, v, off);
        if (l == 0) ws[w] = v;
        __syncthreads();
        if (t < 32) {
            int v2 = ws[t];
#pragma unroll
            for (int off = 16; off; off >>= 1) v2 += __shfl_down_sync(~0u, v2, off);
            if (t == 0) s_off = v2;
        }
        __syncthreads();
    }

    int i = blockIdx.x * 1024 + t;
    int d = (i < NV) ? g_deg[i] : 0;
    int s = d;
#pragma unroll
    for (int off = 1; off < 32; off <<= 1) {
        int u = __shfl_up_sync(~0u, s, off);
        if (l >= off) s += u;
    }
    __syncthreads();                 // ws reuse barrier
    if (l == 31) ws[w] = s;
    __syncthreads();
    if (t < 32) {
        int v = ws[t];
#pragma unroll
        for (int off = 1; off < 32; off <<= 1) {
            int u = __shfl_up_sync(~0u, v, off);
            if (t >= off) v += u;
        }
        ws[t] = v;
    }
    __syncthreads();
    int incl = s + (w ? ws[w - 1] : 0) + s_off;
    if (i < NV) {
        g_start[i] = incl - d;
        g_inv[i]   = 1.0f / (float)(d + 1);
    }
}

// CSR fill, ATOMIC-FREE: slot = start[dst] + precomputed rank. Tail blocks
// re-zero g_deg for the next graph replay (its last reader, scan, is done).
__global__ void fill_kernel(const int* __restrict__ ei) {
    int b = blockIdx.x;
    if (b < CNT_BLK) {
        int e = b * 256 + threadIdx.x;
        if (e < NE) {
            int s = __ldg(ei + e);
            int d = __ldg(ei + NE + e);
            g_csr[g_start[d] + g_pos[e]] = s;
        }
    } else {
        int i = (b - CNT_BLK) * 256 + threadIdx.x;
        if (i < NV) g_deg[i] = 0;
    }
}

// ---------------------------------------------------------------------------
// Gather-aggregate one node's neighborhood (self + CSR), fp16 in, fp32 acc.
__device__ __forceinline__ float4 aggregate(const __half* __restrict__ hin,
                                            int n, int lane) {
    int beg = g_start[n], end = g_start[n + 1];
    size_t lo = (size_t)lane * 4;
    float4 acc = make_float4(0.f, 0.f, 0.f, 0.f);
    acc_u2(acc, *(const uint2*)(hin + (size_t)n * TT + lo));   // self loop
    int k = beg;
    for (; k + 4 <= end; k += 4) {
        int s0 = g_csr[k], s1 = g_csr[k + 1], s2 = g_csr[k + 2], s3 = g_csr[k + 3];
        uint2 u0 = *(const uint2*)(hin + (size_t)s0 * TT + lo);
        uint2 u1 = *(const uint2*)(hin + (size_t)s1 * TT + lo);
        uint2 u2 = *(const uint2*)(hin + (size_t)s2 * TT + lo);
        uint2 u3 = *(const uint2*)(hin + (size_t)s3 * TT + lo);
        acc_u2(acc, u0); acc_u2(acc, u1); acc_u2(acc, u2); acc_u2(acc, u3);
    }
    for (; k < end; k++)
        acc_u2(acc, *(const uint2*)(hin + (size_t)g_csr[k] * TT + lo));
    return acc;
}

// Fused agg + mean + relu + next conv (layers 1, 2).
__global__ void agg_conv_kernel(const __half* __restrict__ hin,
                                __half* __restrict__ hout,
                                const float* __restrict__ cw,
                                const float* __restrict__ cb,
                                int layer) {
    int n = blockIdx.x * 8 + (threadIdx.x >> 5);
    int lane = threadIdx.x & 31;
    if (n >= NV) return;
    float4 acc = aggregate(hin, n, lane);
    float inv = g_inv[n];
    float4 v;
    v.x = fmaxf(acc.x * inv, 0.f);
    v.y = fmaxf(acc.y * inv, 0.f);
    v.z = fmaxf(acc.z * inv, 0.f);
    v.w = fmaxf(acc.w * inv, 0.f);
    float wt[KK];
#pragma unroll
    for (int q = 0; q < KK; q++) wt[q] = cw[layer * KK + q];
    v = conv_shfl(v, wt, cb[layer], lane);
    store_row(hout, n, lane, v);
}

// Fused final agg + mean + relu + output matvec with flat-reshape semantics:
// value of node n at time t sits at flat f = n*128+t of x.reshape(128, NV);
// contributes to out[i = f/NV, c] with weight W[c*NV + (f%NV)].
// Fast path: whole node-row inside one output row (all but 127 nodes).
__global__ void agg_out_kernel(const __half* __restrict__ hin,
                               const float* __restrict__ W,
                               float* __restrict__ out) {
    __shared__ float sm[8][TT * 3];   // per-warp accumulator banks
    int w = threadIdx.x >> 5, lane = threadIdx.x & 31;
    for (int i = threadIdx.x; i < 8 * TT * 3; i += 256)
        ((float*)sm)[i] = 0.f;
    __syncthreads();

    int stride = gridDim.x * 8;
    for (int n = blockIdx.x * 8 + w; n < NV; n += stride) {
        float4 acc = aggregate(hin, n, lane);
        float inv = g_inv[n];
        float v[4];
        v[0] = fmaxf(acc.x * inv, 0.f);
        v[1] = fmaxf(acc.y * inv, 0.f);
        v[2] = fmaxf(acc.z * inv, 0.f);
        v[3] = fmaxf(acc.w * inv, 0.f);

        int fbase = n * TT;              // flat index of t=0
        int i0 = fbase / NV;
        int j0 = fbase - i0 * NV;        // column of t=0 (multiple of 4)

        if (j0 + TT <= NV) {
            // Fast path: single output row; coalesced float4 W loads.
            int j = j0 + lane * 4;
            float4 w0 = *(const float4*)(W + j);
            float4 w1 = *(const float4*)(W + NV + j);
            float4 w2 = *(const float4*)(W + 2 * NV + j);
            float s0 = v[0] * w0.x + v[1] * w0.y + v[2] * w0.z + v[3] * w0.w;
            float s1 = v[0] * w1.x + v[1] * w1.y + v[2] * w1.z + v[3] * w1.w;
            float s2 = v[0] * w2.x + v[1] * w2.y + v[2] * w2.z + v[3] * w2.w;
#pragma unroll
            for (int off = 16; off; off >>= 1) {
                s0 += __shfl_down_sync(~0u, s0, off);
                s1 += __shfl_down_sync(~0u, s1, off);
                s2 += __shfl_down_sync(~0u, s2, off);
            }
            if (lane == 0) {
                sm[w][i0 * 3 + 0] += s0;
                sm[w][i0 * 3 + 1] += s1;
                sm[w][i0 * 3 + 2] += s2;
            }
        } else {
            // Slow path: node-row straddles an output-row boundary.
            int B = (i0 + 1) * NV;
            int f = fbase + lane * 4;
            float s0[3] = {0.f, 0.f, 0.f}, s1[3] = {0.f, 0.f, 0.f};
#pragma unroll
            for (int q = 0; q < 4; q++) {
                int fq = f + q;
                bool hi = fq >= B;
                int j = fq - (hi ? B : i0 * NV);
                float w0 = __ldg(W + j);
                float w1 = __ldg(W + NV + j);
                float w2 = __ldg(W + 2 * NV + j);
                if (hi) { s1[0] += v[q] * w0; s1[1] += v[q] * w1; s1[2] += v[q] * w2; }
                else    { s0[0] += v[q] * w0; s0[1] += v[q] * w1; s0[2] += v[q] * w2; }
            }
#pragma unroll
            for (int off = 16; off; off >>= 1) {
                s0[0] += __shfl_down_sync(~0u, s0[0], off);
                s0[1] += __shfl_down_sync(~0u, s0[1], off);
                s0[2] += __shfl_down_sync(~0u, s0[2], off);
                s1[0] += __shfl_down_sync(~0u, s1[0], off);
                s1[1] += __shfl_down_sync(~0u, s1[1], off);
                s1[2] += __shfl_down_sync(~0u, s1[2], off);
            }
            if (lane == 0) {
                sm[w][i0 * 3 + 0] += s0[0];
                sm[w][i0 * 3 + 1] += s0[1];
                sm[w][i0 * 3 + 2] += s0[2];
                sm[w][(i0 + 1) * 3 + 0] += s1[0];
                sm[w][(i0 + 1) * 3 + 1] += s1[1];
                sm[w][(i0 + 1) * 3 + 2] += s1[2];
            }
        }
    }
    __syncthreads();
    for (int i = threadIdx.x; i < TT * 3; i += 256) {
        float s = 0.f;
#pragma unroll
        for (int ww = 0; ww < 8; ww++) s += sm[ww][i];
        atomicAdd(&out[i], s);
    }
}

// ---------------------------------------------------------------------------
extern "C" void kernel_launch(void* const* d_in, const int* in_sizes, int n_in,
                              void* d_out, int out_size) {
    const float* x  = (const float*)d_in[0];
    const int*   ei = (const int*)  d_in[1];
    const float* cw = (const float*)d_in[2];
    const float* cb = (const float*)d_in[3];
    const float* W  = (const float*)d_in[4];
    const float* bo = (const float*)d_in[5];
    float* out = (float*)d_out;

    __half *hA, *hB;
    cudaGetSymbolAddress((void**)&hA, g_hA);
    cudaGetSymbolAddress((void**)&hB, g_hB);

    // CSR build; g_deg is zero (load-time init on call 1, re-zeroed by
    // fill_kernel's tail blocks on every call for graph replays).
    count_conv0_kernel<<<CNT_BLK + CONV_BLK, 256>>>(ei, bo, out, x, cw, cb, hA);
    scan_kernel<<<NCHUNK, 1024>>>();
    fill_kernel<<<CNT_BLK + ZERO_BLK, 256>>>(ei);

    int gagg = (NV + 7) / 8;
    agg_conv_kernel<<<gagg, 256>>>(hA, hB, cw, cb, 1);
    agg_conv_kernel<<<gagg, 256>>>(hB, hA, cw, cb, 2);
    agg_out_kernel<<<1184, 256>>>(hA, W, out);
}